// round 2
// baseline (speedup 1.0000x reference)
#include <cuda_runtime.h>

#define N_NODES 50000
#define N_EDGES 800000
#define D_IN    256
#define D_HID   128
#define D_RAW   16
#define TILE_E  128
#define LN_EPS  1e-5f

static_assert(N_EDGES % TILE_E == 0, "edge tiling assumes exact division");

// ---------------- scratch (device globals; no runtime allocation) ----------
__device__ float g_W2L[D_HID * D_IN];              // ew2 @ lew  (128x256)
__device__ float g_b2l[D_IN];                      // eb2 @ lew
__device__ float g_h[(size_t)N_NODES * D_IN];      // x + aggr (atomic target)
__device__ float g_t[(size_t)N_NODES * D_IN];      // relu(LN(h@w1+b1))
__device__ int   g_is64;                           // edge_index dtype flag

// ---------------- K-1: detect edge_index dtype ------------------------------
// int64 little-endian values in [0, 50000) have the upper 32-bit word == 0.
// For int32 index data the odds that 64 consecutive odd words are all zero
// are ~(1/50000)^64. One thread, deterministic, graph-capturable.
__global__ void detect_idx_kernel(const int* __restrict__ ei32) {
    if (threadIdx.x == 0 && blockIdx.x == 0) {
        int is64 = 1;
        for (int i = 0; i < 64; i++)
            if (ei32[2 * i + 1] != 0) { is64 = 0; break; }
        g_is64 = is64;
    }
}

// ---------------- K0: fold ew2 @ lew ---------------------------------------
__global__ void precompute_kernel(const float* __restrict__ ew2,
                                  const float* __restrict__ lew,
                                  const float* __restrict__ eb2) {
    int idx = blockIdx.x * blockDim.x + threadIdx.x;   // 0..32767
    int i = idx >> 8;      // row of ew2 (0..127)
    int j = idx & 255;     // col (0..255)
    float s = 0.f;
#pragma unroll 8
    for (int k = 0; k < D_HID; k++)
        s = fmaf(ew2[i * D_HID + k], lew[k * D_IN + j], s);
    g_W2L[i * D_IN + j] = s;
    if (idx < D_IN) {
        float b = 0.f;
        for (int k = 0; k < D_HID; k++)
            b = fmaf(eb2[k], lew[k * D_IN + idx], b);
        g_b2l[idx] = b;
    }
}

// ---------------- K1: g_h = x ----------------------------------------------
__global__ void init_h_kernel(const float* __restrict__ x) {
    const size_t total = (size_t)N_NODES * D_IN / 4;
    const float4* xs = (const float4*)x;
    float4* hs = (float4*)g_h;
    for (size_t i = (size_t)blockIdx.x * blockDim.x + threadIdx.x; i < total;
         i += (size_t)gridDim.x * blockDim.x)
        hs[i] = xs[i];
}

// ---------------- K2: fused edge MLP + gather + scatter --------------------
// Per tile of 128 edges:
//   h  = relu(raw @ ew1 + eb1)                     [128 x 128]   (smem)
//   emb= (pol+.01)*(h @ W2L + b2l) + leb           [128 x 256]   (regs)
//   atomicAdd(g_h[dst], relu(x[src] + emb))
__global__ __launch_bounds__(512, 1)
void edge_kernel(const float* __restrict__ x,
                 const void* __restrict__ ei_raw,
                 const float* __restrict__ ea,
                 const float* __restrict__ ew1,
                 const float* __restrict__ eb1,
                 const float* __restrict__ leb) {
    extern __shared__ float sm[];
    float* s_w2l = sm;                               // 128*256
    float* s_ew1 = s_w2l + D_HID * D_IN;             // 16*128
    float* s_eb1 = s_ew1 + D_RAW * D_HID;            // 128
    float* s_b2l = s_eb1 + D_HID;                    // 256
    float* s_leb = s_b2l + D_IN;                     // 256
    float* s_h   = s_leb + D_IN;                     // 128*128
    float* s_raw = s_h + TILE_E * D_HID;             // 128*16
    float* s_pol = s_raw + TILE_E * D_RAW;           // 128
    int*   s_src = (int*)(s_pol + TILE_E);           // 128
    int*   s_dst = s_src + TILE_E;                   // 128

    const int tid = threadIdx.x;
    const int is64 = g_is64;
    const long long* ei64 = (const long long*)ei_raw;
    const int*       ei32 = (const int*)ei_raw;

    // stage weights once per (persistent) block
    for (int i = tid; i < D_HID * D_IN; i += 512) s_w2l[i] = g_W2L[i];
    for (int i = tid; i < D_RAW * D_HID; i += 512) s_ew1[i] = ew1[i];
    if (tid < D_HID) s_eb1[tid] = eb1[tid];
    if (tid < D_IN) { s_b2l[tid] = g_b2l[tid]; s_leb[tid] = leb[tid]; }
    __syncthreads();

    const int numTiles = N_EDGES / TILE_E;
    for (int tile = blockIdx.x; tile < numTiles; tile += gridDim.x) {
        const int e0 = tile * TILE_E;

        // ---- load edge data ----
        for (int i = tid; i < TILE_E * 17; i += 512) {
            int le = i / 17, c = i % 17;
            float v = ea[(size_t)(e0 + le) * 17 + c];
            if (c == 0) s_pol[le] = fminf(fmaxf(v, 0.f), 1.f) + 0.01f;
            else        s_raw[le * D_RAW + (c - 1)] = v;
        }
        for (int i = tid; i < TILE_E; i += 512) {
            int sv, dv;
            if (is64) {
                sv = (int)ei64[e0 + i];
                dv = (int)ei64[N_EDGES + e0 + i];
            } else {
                sv = ei32[e0 + i];
                dv = ei32[N_EDGES + e0 + i];
            }
            s_src[i] = min(max(sv, 0), N_NODES - 1);
            s_dst[i] = min(max(dv, 0), N_NODES - 1);
        }
        __syncthreads();

        // ---- stage 1: s_h = relu(raw @ ew1 + eb1) ----
        {
            const int eg = tid >> 4;           // 32 groups x 4 edges
            const int cg = tid & 15;           // 16 groups x 8 cols
            const int col0 = cg * 8;
            float acc[4][8];
#pragma unroll
            for (int i = 0; i < 4; i++)
#pragma unroll
                for (int j = 0; j < 8; j++) acc[i][j] = s_eb1[col0 + j];
#pragma unroll
            for (int k = 0; k < D_RAW; k++) {
                float w[8];
#pragma unroll
                for (int j = 0; j < 8; j++) w[j] = s_ew1[k * D_HID + col0 + j];
#pragma unroll
                for (int i = 0; i < 4; i++) {
                    float r = s_raw[(eg * 4 + i) * D_RAW + k];
#pragma unroll
                    for (int j = 0; j < 8; j++) acc[i][j] = fmaf(r, w[j], acc[i][j]);
                }
            }
#pragma unroll
            for (int i = 0; i < 4; i++)
#pragma unroll
                for (int j = 0; j < 8; j++)
                    s_h[(eg * 4 + i) * D_HID + col0 + j] = fmaxf(acc[i][j], 0.f);
        }
        __syncthreads();

        // ---- stage 2+3: emb GEMM + gather + relu + scatter ----
        {
            const int lane = tid & 31;         // strided cols: col = j*32 + lane
            const int eg   = tid >> 5;         // 16 groups x 8 edges
            float acc[8][8];
#pragma unroll
            for (int i = 0; i < 8; i++)
#pragma unroll
                for (int j = 0; j < 8; j++) acc[i][j] = 0.f;

#pragma unroll 2
            for (int k = 0; k < D_HID; k++) {
                float w[8];
#pragma unroll
                for (int j = 0; j < 8; j++) w[j] = s_w2l[k * D_IN + j * 32 + lane];
#pragma unroll
                for (int i = 0; i < 8; i++) {
                    float hv = s_h[(eg * 8 + i) * D_HID + k];
#pragma unroll
                    for (int j = 0; j < 8; j++) acc[i][j] = fmaf(hv, w[j], acc[i][j]);
                }
            }

            float eb[8], lb[8];
#pragma unroll
            for (int j = 0; j < 8; j++) {
                eb[j] = s_b2l[j * 32 + lane];
                lb[j] = s_leb[j * 32 + lane];
            }
#pragma unroll
            for (int i = 0; i < 8; i++) {
                const int le = eg * 8 + i;
                const float s = s_pol[le];
                const float* xr = x + (size_t)s_src[le] * D_IN;
                float* hd = g_h + (size_t)s_dst[le] * D_IN;
#pragma unroll
                for (int j = 0; j < 8; j++) {
                    const int col = j * 32 + lane;      // warp-coalesced 128B
                    float emb = fmaf(s, acc[i][j] + eb[j], lb[j]);
                    float msg = fmaxf(emb + __ldg(xr + col), 0.f);
                    atomicAdd(hd + col, msg);
                }
            }
        }
        __syncthreads();
    }
}

// ---------------- K3: h1 = LN(g_h @ w1 + b1); g_t = relu(h1) ---------------
#define ROWS_B 64
__global__ __launch_bounds__(256)
void node1_kernel(const float* __restrict__ w1, const float* __restrict__ b1,
                  const float* __restrict__ ln_g, const float* __restrict__ ln_b) {
    __shared__ float s_a[ROWS_B * 32];
    __shared__ float s_w[32 * D_IN];
    const int tid = threadIdx.x;
    const int r0 = blockIdx.x * ROWS_B;
    const int eg = tid >> 5, cg = tid & 31, col0 = cg * 8;
    float acc[8][8];
#pragma unroll
    for (int i = 0; i < 8; i++)
#pragma unroll
        for (int j = 0; j < 8; j++) acc[i][j] = 0.f;

    for (int kc = 0; kc < D_IN; kc += 32) {
        for (int i = tid; i < ROWS_B * 32; i += 256) {
            int r = i >> 5, k = i & 31;
            int rr = min(r0 + r, N_NODES - 1);
            s_a[i] = g_h[(size_t)rr * D_IN + kc + k];
        }
        for (int i = tid; i < 32 * D_IN; i += 256) {
            int k = i >> 8, c = i & 255;
            s_w[i] = w1[(size_t)(kc + k) * D_IN + c];
        }
        __syncthreads();
#pragma unroll 4
        for (int k = 0; k < 32; k++) {
            float4 wa = *(const float4*)&s_w[k * D_IN + col0];
            float4 wb = *(const float4*)&s_w[k * D_IN + col0 + 4];
#pragma unroll
            for (int i = 0; i < 8; i++) {
                float a = s_a[(eg * 8 + i) * 32 + k];
                acc[i][0] = fmaf(a, wa.x, acc[i][0]);
                acc[i][1] = fmaf(a, wa.y, acc[i][1]);
                acc[i][2] = fmaf(a, wa.z, acc[i][2]);
                acc[i][3] = fmaf(a, wa.w, acc[i][3]);
                acc[i][4] = fmaf(a, wb.x, acc[i][4]);
                acc[i][5] = fmaf(a, wb.y, acc[i][5]);
                acc[i][6] = fmaf(a, wb.z, acc[i][6]);
                acc[i][7] = fmaf(a, wb.w, acc[i][7]);
            }
        }
        __syncthreads();
    }

    float4 b1a = *(const float4*)&b1[col0];
    float4 b1b = *(const float4*)&b1[col0 + 4];
    float4 ga  = *(const float4*)&ln_g[col0];
    float4 gb  = *(const float4*)&ln_g[col0 + 4];
    float4 ba  = *(const float4*)&ln_b[col0];
    float4 bb  = *(const float4*)&ln_b[col0 + 4];
    const float bv[8] = {b1a.x,b1a.y,b1a.z,b1a.w,b1b.x,b1b.y,b1b.z,b1b.w};
    const float gv[8] = {ga.x,ga.y,ga.z,ga.w,gb.x,gb.y,gb.z,gb.w};
    const float lv[8] = {ba.x,ba.y,ba.z,ba.w,bb.x,bb.y,bb.z,bb.w};

#pragma unroll
    for (int i = 0; i < 8; i++) {
        const int row = r0 + eg * 8 + i;
        float v[8];
        float ps = 0.f;
#pragma unroll
        for (int j = 0; j < 8; j++) { v[j] = acc[i][j] + bv[j]; ps += v[j]; }
#pragma unroll
        for (int m = 16; m >= 1; m >>= 1) ps += __shfl_xor_sync(0xffffffffu, ps, m);
        const float mu = ps * (1.f / D_IN);
        float vs = 0.f;
#pragma unroll
        for (int j = 0; j < 8; j++) { float d = v[j] - mu; vs = fmaf(d, d, vs); }
#pragma unroll
        for (int m = 16; m >= 1; m >>= 1) vs += __shfl_xor_sync(0xffffffffu, vs, m);
        const float rstd = rsqrtf(vs * (1.f / D_IN) + LN_EPS);
        if (row < N_NODES) {
            float o[8];
#pragma unroll
            for (int j = 0; j < 8; j++)
                o[j] = fmaxf(fmaf((v[j] - mu) * rstd, gv[j], lv[j]), 0.f);
            float* dst = g_t + (size_t)row * D_IN + col0;
            *(float4*)dst       = make_float4(o[0], o[1], o[2], o[3]);
            *(float4*)(dst + 4) = make_float4(o[4], o[5], o[6], o[7]);
        }
    }
}

// ---------------- K4: out = g_t @ w2 + b2 ----------------------------------
__global__ __launch_bounds__(256)
void node2_kernel(const float* __restrict__ w2, const float* __restrict__ b2,
                  float* __restrict__ out) {
    __shared__ float s_a[ROWS_B * 32];
    __shared__ float s_w[32 * D_IN];
    const int tid = threadIdx.x;
    const int r0 = blockIdx.x * ROWS_B;
    const int eg = tid >> 5, cg = tid & 31, col0 = cg * 8;
    float acc[8][8];
#pragma unroll
    for (int i = 0; i < 8; i++)
#pragma unroll
        for (int j = 0; j < 8; j++) acc[i][j] = 0.f;

    for (int kc = 0; kc < D_IN; kc += 32) {
        for (int i = tid; i < ROWS_B * 32; i += 256) {
            int r = i >> 5, k = i & 31;
            int rr = min(r0 + r, N_NODES - 1);
            s_a[i] = g_t[(size_t)rr * D_IN + kc + k];
        }
        for (int i = tid; i < 32 * D_IN; i += 256) {
            int k = i >> 8, c = i & 255;
            s_w[i] = w2[(size_t)(kc + k) * D_IN + c];
        }
        __syncthreads();
#pragma unroll 4
        for (int k = 0; k < 32; k++) {
            float4 wa = *(const float4*)&s_w[k * D_IN + col0];
            float4 wb = *(const float4*)&s_w[k * D_IN + col0 + 4];
#pragma unroll
            for (int i = 0; i < 8; i++) {
                float a = s_a[(eg * 8 + i) * 32 + k];
                acc[i][0] = fmaf(a, wa.x, acc[i][0]);
                acc[i][1] = fmaf(a, wa.y, acc[i][1]);
                acc[i][2] = fmaf(a, wa.z, acc[i][2]);
                acc[i][3] = fmaf(a, wa.w, acc[i][3]);
                acc[i][4] = fmaf(a, wb.x, acc[i][4]);
                acc[i][5] = fmaf(a, wb.y, acc[i][5]);
                acc[i][6] = fmaf(a, wb.z, acc[i][6]);
                acc[i][7] = fmaf(a, wb.w, acc[i][7]);
            }
        }
        __syncthreads();
    }

    float4 b2a = *(const float4*)&b2[col0];
    float4 b2b = *(const float4*)&b2[col0 + 4];
    const float bv[8] = {b2a.x,b2a.y,b2a.z,b2a.w,b2b.x,b2b.y,b2b.z,b2b.w};
#pragma unroll
    for (int i = 0; i < 8; i++) {
        const int row = r0 + eg * 8 + i;
        if (row < N_NODES) {
            float* dst = out + (size_t)row * D_IN + col0;
            *(float4*)dst       = make_float4(acc[i][0] + bv[0], acc[i][1] + bv[1],
                                              acc[i][2] + bv[2], acc[i][3] + bv[3]);
            *(float4*)(dst + 4) = make_float4(acc[i][4] + bv[4], acc[i][5] + bv[5],
                                              acc[i][6] + bv[6], acc[i][7] + bv[7]);
        }
    }
}

// ---------------- launcher --------------------------------------------------
extern "C" void kernel_launch(void* const* d_in, const int* in_sizes, int n_in,
                              void* d_out, int out_size) {
    const float* x    = (const float*)d_in[0];
    const void*  ei   = d_in[1];
    const float* ea   = (const float*)d_in[2];
    const float* ew1  = (const float*)d_in[3];
    const float* eb1  = (const float*)d_in[4];
    const float* ew2  = (const float*)d_in[5];
    const float* eb2  = (const float*)d_in[6];
    const float* lew  = (const float*)d_in[7];
    const float* leb  = (const float*)d_in[8];
    const float* w1   = (const float*)d_in[9];
    const float* b1   = (const float*)d_in[10];
    const float* ln_g = (const float*)d_in[11];
    const float* ln_b = (const float*)d_in[12];
    const float* w2   = (const float*)d_in[13];
    const float* b2   = (const float*)d_in[14];
    float* out = (float*)d_out;

    // smem: (32768+2048+128+256+256+16384+2048+128)*4 + 128*2*4 = 217088 B
    const int EDGE_SMEM = 217088;
    cudaFuncSetAttribute(edge_kernel, cudaFuncAttributeMaxDynamicSharedMemorySize,
                         EDGE_SMEM);

    detect_idx_kernel<<<1, 32>>>((const int*)ei);
    precompute_kernel<<<128, 256>>>(ew2, lew, eb2);
    init_h_kernel<<<1184, 256>>>(x);
    edge_kernel<<<148, 512, EDGE_SMEM>>>(x, ei, ea, ew1, eb1, leb);
    node1_kernel<<<(N_NODES + ROWS_B - 1) / ROWS_B, 256>>>(w1, b1, ln_g, ln_b);
    node2_kernel<<<(N_NODES + ROWS_B - 1) / ROWS_B, 256>>>(w2, b2, out);
}

// round 3
// speedup vs baseline: 1.0206x; 1.0206x over previous
#include <cuda_runtime.h>

#define N_NODES 50000
#define N_EDGES 800000
#define D_IN    256
#define D_HID   128
#define D_RAW   16
#define TILE_E  128
#define LN_EPS  1e-5f

static_assert(N_EDGES % TILE_E == 0, "edge tiling assumes exact division");

// ---------------- packed f32x2 helpers (FFMA2: 2 fp32 FMA / instruction) ----
__device__ __forceinline__ unsigned long long pack2(float lo, float hi) {
    unsigned long long r;
    asm("mov.b64 %0, {%1, %2};" : "=l"(r) : "f"(lo), "f"(hi));
    return r;
}
__device__ __forceinline__ void fma2(unsigned long long& d,
                                     unsigned long long a,
                                     unsigned long long b) {
    asm("fma.rn.f32x2 %0, %1, %2, %0;" : "+l"(d) : "l"(a), "l"(b));
}
__device__ __forceinline__ float2 unpack2(unsigned long long v) {
    float2 f;
    asm("mov.b64 {%0, %1}, %2;" : "=f"(f.x), "=f"(f.y) : "l"(v));
    return f;
}

// ---------------- scratch (device globals; no runtime allocation) ----------
__device__ float g_W2L[D_HID * D_IN];              // ew2 @ lew  (128x256)
__device__ float g_b2l[D_IN];                      // eb2 @ lew
__device__ float g_h[(size_t)N_NODES * D_IN];      // x + aggr (atomic target)
__device__ float g_t[(size_t)N_NODES * D_IN];      // relu(LN(h@w1+b1))
__device__ int   g_is64;                           // edge_index dtype flag

// ---------------- K-1: detect edge_index dtype ------------------------------
__global__ void detect_idx_kernel(const int* __restrict__ ei32) {
    if (threadIdx.x == 0 && blockIdx.x == 0) {
        int is64 = 1;
        for (int i = 0; i < 64; i++)
            if (ei32[2 * i + 1] != 0) { is64 = 0; break; }
        g_is64 = is64;
    }
}

// ---------------- K0: fold ew2 @ lew ---------------------------------------
__global__ void precompute_kernel(const float* __restrict__ ew2,
                                  const float* __restrict__ lew,
                                  const float* __restrict__ eb2) {
    int idx = blockIdx.x * blockDim.x + threadIdx.x;   // 0..32767
    int i = idx >> 8;      // row of ew2 (0..127)
    int j = idx & 255;     // col (0..255)
    float s = 0.f;
#pragma unroll 8
    for (int k = 0; k < D_HID; k++)
        s = fmaf(ew2[i * D_HID + k], lew[k * D_IN + j], s);
    g_W2L[i * D_IN + j] = s;
    if (idx < D_IN) {
        float b = 0.f;
        for (int k = 0; k < D_HID; k++)
            b = fmaf(eb2[k], lew[k * D_IN + idx], b);
        g_b2l[idx] = b;
    }
}

// ---------------- K1: g_h = x ----------------------------------------------
__global__ void init_h_kernel(const float* __restrict__ x) {
    const size_t total = (size_t)N_NODES * D_IN / 4;
    const float4* xs = (const float4*)x;
    float4* hs = (float4*)g_h;
    for (size_t i = (size_t)blockIdx.x * blockDim.x + threadIdx.x; i < total;
         i += (size_t)gridDim.x * blockDim.x)
        hs[i] = xs[i];
}

// ---------------- K2: fused edge MLP + gather + scatter --------------------
// Per tile of 128 edges:
//   h  = relu(raw @ ew1 + eb1)                     [128 x 128]   (smem)
//   emb= (pol+.01)*(h @ W2L + b2l) + leb           [128 x 256]   (f32x2 regs)
//   atomicAdd(g_h[dst], relu(x[src] + emb))
__global__ __launch_bounds__(512, 1)
void edge_kernel(const float* __restrict__ x,
                 const void* __restrict__ ei_raw,
                 const float* __restrict__ ea,
                 const float* __restrict__ ew1,
                 const float* __restrict__ eb1,
                 const float* __restrict__ leb) {
    extern __shared__ float sm[];
    float* s_w2l = sm;                               // 128*256
    float* s_ew1 = s_w2l + D_HID * D_IN;             // 16*128
    float* s_eb1 = s_ew1 + D_RAW * D_HID;            // 128
    float* s_b2l = s_eb1 + D_HID;                    // 256
    float* s_leb = s_b2l + D_IN;                     // 256
    float* s_h   = s_leb + D_IN;                     // 128*128
    float* s_raw = s_h + TILE_E * D_HID;             // 128*16
    float* s_pol = s_raw + TILE_E * D_RAW;           // 128
    int*   s_src = (int*)(s_pol + TILE_E);           // 128
    int*   s_dst = s_src + TILE_E;                   // 128

    const int tid = threadIdx.x;
    const int is64 = g_is64;
    const long long* ei64 = (const long long*)ei_raw;
    const int*       ei32 = (const int*)ei_raw;

    // stage weights once per (persistent) block
    for (int i = tid; i < D_HID * D_IN; i += 512) s_w2l[i] = g_W2L[i];
    for (int i = tid; i < D_RAW * D_HID; i += 512) s_ew1[i] = ew1[i];
    if (tid < D_HID) s_eb1[tid] = eb1[tid];
    if (tid < D_IN) { s_b2l[tid] = g_b2l[tid]; s_leb[tid] = leb[tid]; }
    __syncthreads();

    const int lane = tid & 31;
    const int eg   = tid >> 5;                       // 16 groups x 8 edges
    // bias/leb pairs for this lane's 4 column-pairs (invariant across tiles)
    float2 ebp[4], lbp[4];
#pragma unroll
    for (int p = 0; p < 4; p++) {
        ebp[p] = *(const float2*)&s_b2l[p * 64 + lane * 2];
        lbp[p] = *(const float2*)&s_leb[p * 64 + lane * 2];
    }

    const int numTiles = N_EDGES / TILE_E;
    for (int tile = blockIdx.x; tile < numTiles; tile += gridDim.x) {
        const int e0 = tile * TILE_E;

        // ---- load edge data ----
        for (int i = tid; i < TILE_E * 17; i += 512) {
            int le = i / 17, c = i % 17;
            float v = ea[(size_t)(e0 + le) * 17 + c];
            if (c == 0) s_pol[le] = fminf(fmaxf(v, 0.f), 1.f) + 0.01f;
            else        s_raw[le * D_RAW + (c - 1)] = v;
        }
        for (int i = tid; i < TILE_E; i += 512) {
            int sv, dv;
            if (is64) {
                sv = (int)ei64[e0 + i];
                dv = (int)ei64[N_EDGES + e0 + i];
            } else {
                sv = ei32[e0 + i];
                dv = ei32[N_EDGES + e0 + i];
            }
            s_src[i] = min(max(sv, 0), N_NODES - 1);
            s_dst[i] = min(max(dv, 0), N_NODES - 1);
        }
        __syncthreads();

        // ---- stage 1: s_h = relu(raw @ ew1 + eb1) ----
        {
            const int eg1 = tid >> 4;          // 32 groups x 4 edges
            const int cg1 = tid & 15;          // 16 groups x 8 cols
            const int col0 = cg1 * 8;
            float acc[4][8];
#pragma unroll
            for (int i = 0; i < 4; i++)
#pragma unroll
                for (int j = 0; j < 8; j++) acc[i][j] = s_eb1[col0 + j];
#pragma unroll
            for (int k = 0; k < D_RAW; k++) {
                float w[8];
#pragma unroll
                for (int j = 0; j < 8; j++) w[j] = s_ew1[k * D_HID + col0 + j];
#pragma unroll
                for (int i = 0; i < 4; i++) {
                    float r = s_raw[(eg1 * 4 + i) * D_RAW + k];
#pragma unroll
                    for (int j = 0; j < 8; j++) acc[i][j] = fmaf(r, w[j], acc[i][j]);
                }
            }
#pragma unroll
            for (int i = 0; i < 4; i++)
#pragma unroll
                for (int j = 0; j < 8; j++)
                    s_h[(eg1 * 4 + i) * D_HID + col0 + j] = fmaxf(acc[i][j], 0.f);
        }
        __syncthreads();

        // ---- stage 2+3: emb GEMM (f32x2) + gather + relu + scatter ----
        {
            unsigned long long acc2[8][4];
#pragma unroll
            for (int i = 0; i < 8; i++)
#pragma unroll
                for (int p = 0; p < 4; p++) acc2[i][p] = 0ull;

#pragma unroll 2
            for (int k = 0; k < D_HID; k++) {
                const unsigned long long* wrow =
                    (const unsigned long long*)(s_w2l + k * D_IN);
                unsigned long long w2[4];
#pragma unroll
                for (int p = 0; p < 4; p++) w2[p] = wrow[p * 32 + lane];
#pragma unroll
                for (int i = 0; i < 8; i++) {
                    float hv = s_h[(eg * 8 + i) * D_HID + k];
                    unsigned long long hv2 = pack2(hv, hv);
#pragma unroll
                    for (int p = 0; p < 4; p++) fma2(acc2[i][p], hv2, w2[p]);
                }
            }

#pragma unroll
            for (int i = 0; i < 8; i++) {
                const int le = eg * 8 + i;
                const float s = s_pol[le];
                const float* xr = x + (size_t)s_src[le] * D_IN;
                float* hd = g_h + (size_t)s_dst[le] * D_IN;
#pragma unroll
                for (int p = 0; p < 4; p++) {
                    const int col = p * 64 + lane * 2;
                    float2 a  = unpack2(acc2[i][p]);
                    float2 xv = *(const float2*)(xr + col);
                    float m0 = fmaxf(fmaf(s, a.x + ebp[p].x, lbp[p].x) + xv.x, 0.f);
                    float m1 = fmaxf(fmaf(s, a.y + ebp[p].y, lbp[p].y) + xv.y, 0.f);
                    atomicAdd(hd + col,     m0);
                    atomicAdd(hd + col + 1, m1);
                }
            }
        }
        __syncthreads();
    }
}

// ---------------- K3: h1 = LN(g_h @ w1 + b1); g_t = relu(h1) ---------------
#define ROWS_B 64
__global__ __launch_bounds__(256)
void node1_kernel(const float* __restrict__ w1, const float* __restrict__ b1,
                  const float* __restrict__ ln_g, const float* __restrict__ ln_b) {
    __shared__ float s_a[ROWS_B * 32];
    __shared__ float s_w[32 * D_IN];
    const int tid = threadIdx.x;
    const int r0 = blockIdx.x * ROWS_B;
    const int eg = tid >> 5, cg = tid & 31, col0 = cg * 8;
    unsigned long long acc2[8][4];
#pragma unroll
    for (int i = 0; i < 8; i++)
#pragma unroll
        for (int p = 0; p < 4; p++) acc2[i][p] = 0ull;

    for (int kc = 0; kc < D_IN; kc += 32) {
        for (int i = tid; i < ROWS_B * 32; i += 256) {
            int r = i >> 5, k = i & 31;
            int rr = min(r0 + r, N_NODES - 1);
            s_a[i] = g_h[(size_t)rr * D_IN + kc + k];
        }
        for (int i = tid; i < 32 * D_IN; i += 256) {
            int k = i >> 8, c = i & 255;
            s_w[i] = w1[(size_t)(kc + k) * D_IN + c];
        }
        __syncthreads();
#pragma unroll 4
        for (int k = 0; k < 32; k++) {
            const unsigned long long* wr =
                (const unsigned long long*)&s_w[k * D_IN + col0];
            unsigned long long w0 = wr[0], w1v = wr[1], w2v = wr[2], w3v = wr[3];
#pragma unroll
            for (int i = 0; i < 8; i++) {
                float a = s_a[(eg * 8 + i) * 32 + k];
                unsigned long long a2 = pack2(a, a);
                fma2(acc2[i][0], a2, w0);
                fma2(acc2[i][1], a2, w1v);
                fma2(acc2[i][2], a2, w2v);
                fma2(acc2[i][3], a2, w3v);
            }
        }
        __syncthreads();
    }

    float4 b1a = *(const float4*)&b1[col0];
    float4 b1b = *(const float4*)&b1[col0 + 4];
    float4 ga  = *(const float4*)&ln_g[col0];
    float4 gb  = *(const float4*)&ln_g[col0 + 4];
    float4 ba  = *(const float4*)&ln_b[col0];
    float4 bb  = *(const float4*)&ln_b[col0 + 4];
    const float bv[8] = {b1a.x,b1a.y,b1a.z,b1a.w,b1b.x,b1b.y,b1b.z,b1b.w};
    const float gv[8] = {ga.x,ga.y,ga.z,ga.w,gb.x,gb.y,gb.z,gb.w};
    const float lv[8] = {ba.x,ba.y,ba.z,ba.w,bb.x,bb.y,bb.z,bb.w};

#pragma unroll
    for (int i = 0; i < 8; i++) {
        const int row = r0 + eg * 8 + i;
        float v[8];
#pragma unroll
        for (int p = 0; p < 4; p++) {
            float2 f = unpack2(acc2[i][p]);
            v[2 * p] = f.x; v[2 * p + 1] = f.y;
        }
        float ps = 0.f;
#pragma unroll
        for (int j = 0; j < 8; j++) { v[j] += bv[j]; ps += v[j]; }
#pragma unroll
        for (int m = 16; m >= 1; m >>= 1) ps += __shfl_xor_sync(0xffffffffu, ps, m);
        const float mu = ps * (1.f / D_IN);
        float vs = 0.f;
#pragma unroll
        for (int j = 0; j < 8; j++) { float d = v[j] - mu; vs = fmaf(d, d, vs); }
#pragma unroll
        for (int m = 16; m >= 1; m >>= 1) vs += __shfl_xor_sync(0xffffffffu, vs, m);
        const float rstd = rsqrtf(vs * (1.f / D_IN) + LN_EPS);
        if (row < N_NODES) {
            float o[8];
#pragma unroll
            for (int j = 0; j < 8; j++)
                o[j] = fmaxf(fmaf((v[j] - mu) * rstd, gv[j], lv[j]), 0.f);
            float* dst = g_t + (size_t)row * D_IN + col0;
            *(float4*)dst       = make_float4(o[0], o[1], o[2], o[3]);
            *(float4*)(dst + 4) = make_float4(o[4], o[5], o[6], o[7]);
        }
    }
}

// ---------------- K4: out = g_t @ w2 + b2 ----------------------------------
__global__ __launch_bounds__(256)
void node2_kernel(const float* __restrict__ w2, const float* __restrict__ b2,
                  float* __restrict__ out) {
    __shared__ float s_a[ROWS_B * 32];
    __shared__ float s_w[32 * D_IN];
    const int tid = threadIdx.x;
    const int r0 = blockIdx.x * ROWS_B;
    const int eg = tid >> 5, cg = tid & 31, col0 = cg * 8;
    unsigned long long acc2[8][4];
#pragma unroll
    for (int i = 0; i < 8; i++)
#pragma unroll
        for (int p = 0; p < 4; p++) acc2[i][p] = 0ull;

    for (int kc = 0; kc < D_IN; kc += 32) {
        for (int i = tid; i < ROWS_B * 32; i += 256) {
            int r = i >> 5, k = i & 31;
            int rr = min(r0 + r, N_NODES - 1);
            s_a[i] = g_t[(size_t)rr * D_IN + kc + k];
        }
        for (int i = tid; i < 32 * D_IN; i += 256) {
            int k = i >> 8, c = i & 255;
            s_w[i] = w2[(size_t)(kc + k) * D_IN + c];
        }
        __syncthreads();
#pragma unroll 4
        for (int k = 0; k < 32; k++) {
            const unsigned long long* wr =
                (const unsigned long long*)&s_w[k * D_IN + col0];
            unsigned long long w0 = wr[0], w1v = wr[1], w2v = wr[2], w3v = wr[3];
#pragma unroll
            for (int i = 0; i < 8; i++) {
                float a = s_a[(eg * 8 + i) * 32 + k];
                unsigned long long a2 = pack2(a, a);
                fma2(acc2[i][0], a2, w0);
                fma2(acc2[i][1], a2, w1v);
                fma2(acc2[i][2], a2, w2v);
                fma2(acc2[i][3], a2, w3v);
            }
        }
        __syncthreads();
    }

    float4 b2a = *(const float4*)&b2[col0];
    float4 b2b = *(const float4*)&b2[col0 + 4];
    const float bv[8] = {b2a.x,b2a.y,b2a.z,b2a.w,b2b.x,b2b.y,b2b.z,b2b.w};
#pragma unroll
    for (int i = 0; i < 8; i++) {
        const int row = r0 + eg * 8 + i;
        if (row < N_NODES) {
            float v[8];
#pragma unroll
            for (int p = 0; p < 4; p++) {
                float2 f = unpack2(acc2[i][p]);
                v[2 * p] = f.x + bv[2 * p];
                v[2 * p + 1] = f.y + bv[2 * p + 1];
            }
            float* dst = out + (size_t)row * D_IN + col0;
            *(float4*)dst       = make_float4(v[0], v[1], v[2], v[3]);
            *(float4*)(dst + 4) = make_float4(v[4], v[5], v[6], v[7]);
        }
    }
}

// ---------------- launcher --------------------------------------------------
extern "C" void kernel_launch(void* const* d_in, const int* in_sizes, int n_in,
                              void* d_out, int out_size) {
    const float* x    = (const float*)d_in[0];
    const void*  ei   = d_in[1];
    const float* ea   = (const float*)d_in[2];
    const float* ew1  = (const float*)d_in[3];
    const float* eb1  = (const float*)d_in[4];
    const float* ew2  = (const float*)d_in[5];
    const float* eb2  = (const float*)d_in[6];
    const float* lew  = (const float*)d_in[7];
    const float* leb  = (const float*)d_in[8];
    const float* w1   = (const float*)d_in[9];
    const float* b1   = (const float*)d_in[10];
    const float* ln_g = (const float*)d_in[11];
    const float* ln_b = (const float*)d_in[12];
    const float* w2   = (const float*)d_in[13];
    const float* b2   = (const float*)d_in[14];
    float* out = (float*)d_out;

    // smem: (32768+2048+128+256+256+16384+2048+128)*4 + 128*2*4 = 217088 B
    const int EDGE_SMEM = 217088;
    cudaFuncSetAttribute(edge_kernel, cudaFuncAttributeMaxDynamicSharedMemorySize,
                         EDGE_SMEM);

    detect_idx_kernel<<<1, 32>>>((const int*)ei);
    precompute_kernel<<<128, 256>>>(ew2, lew, eb2);
    init_h_kernel<<<1184, 256>>>(x);
    edge_kernel<<<148, 512, EDGE_SMEM>>>(x, ei, ea, ew1, eb1, leb);
    node1_kernel<<<(N_NODES + ROWS_B - 1) / ROWS_B, 256>>>(w1, b1, ln_g, ln_b);
    node2_kernel<<<(N_NODES + ROWS_B - 1) / ROWS_B, 256>>>(w2, b2, out);
}

// round 5
// speedup vs baseline: 1.5757x; 1.5439x over previous
#include <cuda_runtime.h>
#include <cuda_bf16.h>
#include <cstdint>

#define N_NODES 50000
#define N_EDGES 800000
#define D_IN    256
#define D_HID   128
#define D_RAW   16
#define TILE_E  128
#define LN_EPS  1e-5f

static_assert(N_EDGES % TILE_E == 0, "edge tiling assumes exact division");

// ---------------- packed f32x2 helpers (node kernels) ----------------------
__device__ __forceinline__ unsigned long long pack2(float lo, float hi) {
    unsigned long long r;
    asm("mov.b64 %0, {%1, %2};" : "=l"(r) : "f"(lo), "f"(hi));
    return r;
}
__device__ __forceinline__ void fma2(unsigned long long& d,
                                     unsigned long long a,
                                     unsigned long long b) {
    asm("fma.rn.f32x2 %0, %1, %2, %0;" : "+l"(d) : "l"(a), "l"(b));
}
__device__ __forceinline__ float2 unpack2(unsigned long long v) {
    float2 f;
    asm("mov.b64 {%0, %1}, %2;" : "=f"(f.x), "=f"(f.y) : "l"(v));
    return f;
}

// ---------------- portable warp-MMA helpers (sm_80+ PTX) -------------------
__device__ __forceinline__ uint32_t smem_to_u32(const void* p) {
    uint32_t a;
    asm("{ .reg .u64 t; cvta.to.shared.u64 t, %1; cvt.u32.u64 %0, t; }"
        : "=r"(a) : "l"(p));
    return a;
}
__device__ __forceinline__ void ldsm_x4(uint32_t* r, uint32_t addr) {
    asm volatile("ldmatrix.sync.aligned.m8n8.x4.shared.b16 {%0,%1,%2,%3}, [%4];"
                 : "=r"(r[0]), "=r"(r[1]), "=r"(r[2]), "=r"(r[3]) : "r"(addr));
}
__device__ __forceinline__ void ldsm_x2(uint32_t* r, uint32_t addr) {
    asm volatile("ldmatrix.sync.aligned.m8n8.x2.shared.b16 {%0,%1}, [%2];"
                 : "=r"(r[0]), "=r"(r[1]) : "r"(addr));
}
__device__ __forceinline__ void mma_bf16(float* d, const uint32_t* a,
                                         const uint32_t* b) {
    asm volatile(
        "mma.sync.aligned.m16n8k16.row.col.f32.bf16.bf16.f32 "
        "{%0,%1,%2,%3}, {%4,%5,%6,%7}, {%8,%9}, {%0,%1,%2,%3};"
        : "+f"(d[0]), "+f"(d[1]), "+f"(d[2]), "+f"(d[3])
        : "r"(a[0]), "r"(a[1]), "r"(a[2]), "r"(a[3]), "r"(b[0]), "r"(b[1]));
}
__device__ __forceinline__ void red_v2(float* gptr, float a, float b) {
    asm volatile("red.global.add.v2.f32 [%0], {%1, %2};"
                 :: "l"(gptr), "f"(a), "f"(b) : "memory");
}

// ---------------- scratch (device globals; no runtime allocation) ----------
__device__ float g_b2l[D_IN];                       // eb2 @ lew
__device__ __nv_bfloat16 g_Bh[D_IN * D_HID];        // B[n][k] hi split
__device__ __nv_bfloat16 g_Bl[D_IN * D_HID];        // B[n][k] lo split
__device__ float g_h[(size_t)N_NODES * D_IN];       // x + aggr (atomic target)
__device__ float g_t[(size_t)N_NODES * D_IN];       // relu(LN(h@w1+b1))
__device__ int   g_is64;                            // edge_index dtype flag

// ---------------- K-1: detect edge_index dtype ------------------------------
__global__ void detect_idx_kernel(const int* __restrict__ ei32) {
    if (threadIdx.x == 0 && blockIdx.x == 0) {
        int is64 = 1;
        for (int i = 0; i < 64; i++)
            if (ei32[2 * i + 1] != 0) { is64 = 0; break; }
        g_is64 = is64;
    }
}

// ---------------- K0: fold ew2 @ lew, split to bf16 hi/lo -------------------
__global__ void precompute_kernel(const float* __restrict__ ew2,
                                  const float* __restrict__ lew,
                                  const float* __restrict__ eb2) {
    int idx = blockIdx.x * blockDim.x + threadIdx.x;   // 0..32767
    int k = idx >> 8;      // 0..127 (hid)
    int n = idx & 255;     // 0..255 (out col)
    float s = 0.f;
#pragma unroll 8
    for (int j = 0; j < D_HID; j++)
        s = fmaf(ew2[k * D_HID + j], lew[j * D_IN + n], s);
    __nv_bfloat16 hi = __float2bfloat16(s);
    float lo = s - __bfloat162float(hi);
    g_Bh[n * D_HID + k] = hi;
    g_Bl[n * D_HID + k] = __float2bfloat16(lo);
    if (idx < D_IN) {
        float b = 0.f;
        for (int j = 0; j < D_HID; j++)
            b = fmaf(eb2[j], lew[j * D_IN + idx], b);
        g_b2l[idx] = b;
    }
}

// ---------------- K1: g_h = x ----------------------------------------------
__global__ void init_h_kernel(const float* __restrict__ x) {
    const size_t total = (size_t)N_NODES * D_IN / 4;
    const float4* xs = (const float4*)x;
    float4* hs = (float4*)g_h;
    for (size_t i = (size_t)blockIdx.x * blockDim.x + threadIdx.x; i < total;
         i += (size_t)gridDim.x * blockDim.x)
        hs[i] = xs[i];
}

// ---------------- K2: edge kernel, warp-level bf16x3 mma.sync ---------------
// smem layout (bytes). A/B rows padded to 272 B (136 bf16) -> ldmatrix
// conflict-free (row shift = 4 banks).
#define STRIDE_AB 272
#define OFF_BH   0          // 256*272 = 69632
#define OFF_BL   69632      // 69632
#define OFF_AH   139264     // 128*272 = 34816
#define OFF_AL   174080     // 34816
#define OFF_EW1  208896     // 8192
#define OFF_RAW  217088     // 8192
#define OFF_EB1  225280     // 512
#define OFF_B2L  225792     // 1024
#define OFF_LEB  226816     // 1024
#define OFF_POL  227840     // 512
#define OFF_SRC  228352     // 512
#define OFF_DST  228864     // 512
#define EDGE_SMEM 229376

__global__ __launch_bounds__(512, 1)
void edge_kernel(const float* __restrict__ x,
                 const void* __restrict__ ei_raw,
                 const float* __restrict__ ea,
                 const float* __restrict__ ew1,
                 const float* __restrict__ eb1,
                 const float* __restrict__ leb) {
    extern __shared__ char smem[];
    const uint32_t smem_u = smem_to_u32(smem);
    float* s_ew1 = (float*)(smem + OFF_EW1);
    float* s_raw = (float*)(smem + OFF_RAW);
    float* s_eb1 = (float*)(smem + OFF_EB1);
    float* s_b2l = (float*)(smem + OFF_B2L);
    float* s_leb = (float*)(smem + OFF_LEB);
    float* s_pol = (float*)(smem + OFF_POL);
    int*   s_src = (int*)(smem + OFF_SRC);
    int*   s_dst = (int*)(smem + OFF_DST);

    const int tid = threadIdx.x;
    const int wid = tid >> 5;
    const int lane = tid & 31;
    const int is64 = g_is64;
    const long long* ei64 = (const long long*)ei_raw;
    const int*       ei32 = (const int*)ei_raw;

    // ---- stage B splits (padded rows) + weights once per block ----
    for (int w = tid; w < 256 * 64; w += 512) {      // word = 2 bf16 along k
        int n = w >> 6, k2 = w & 63;
        uint32_t off = (uint32_t)n * STRIDE_AB + (uint32_t)k2 * 4u;
        *(uint32_t*)(smem + OFF_BH + off) = ((const uint32_t*)g_Bh)[w];
        *(uint32_t*)(smem + OFF_BL + off) = ((const uint32_t*)g_Bl)[w];
    }
    for (int i = tid; i < D_RAW * D_HID; i += 512) s_ew1[i] = ew1[i];
    if (tid < D_HID) s_eb1[tid] = eb1[tid];
    if (tid < D_IN) { s_b2l[tid] = g_b2l[tid]; s_leb[tid] = leb[tid]; }
    __syncthreads();

    // warp tile: rows [wm*32, wm*32+32), cols [wn*64, wn*64+64)
    const int wm = wid & 3;
    const int wn = wid >> 2;
    // ldmatrix lane address offsets
    const int l15 = lane & 15;
    const uint32_t a_off = (uint32_t)(wm * 32 + l15) * STRIDE_AB +
                           (uint32_t)(lane >> 4) * 16u;
    const int l7 = lane & 7;
    const uint32_t b_off = (uint32_t)(wn * 64 + l7) * STRIDE_AB +
                           (uint32_t)((lane >> 3) & 1) * 16u;
    const int q  = lane >> 2;          // fragment row within 8
    const int cp = (lane & 3) * 2;     // fragment col pair base

    const int numTiles = N_EDGES / TILE_E;
    for (int tile = blockIdx.x; tile < numTiles; tile += gridDim.x) {
        const int e0 = tile * TILE_E;

        // ---- load edge data ----
        for (int i = tid; i < TILE_E * 17; i += 512) {
            int le = i / 17, c = i % 17;
            float v = ea[(size_t)(e0 + le) * 17 + c];
            if (c == 0) s_pol[le] = fminf(fmaxf(v, 0.f), 1.f) + 0.01f;
            else        s_raw[le * D_RAW + (c - 1)] = v;
        }
        for (int i = tid; i < TILE_E; i += 512) {
            int sv, dv;
            if (is64) {
                sv = (int)ei64[e0 + i];
                dv = (int)ei64[N_EDGES + e0 + i];
            } else {
                sv = ei32[e0 + i];
                dv = ei32[N_EDGES + e0 + i];
            }
            s_src[i] = min(max(sv, 0), N_NODES - 1);
            s_dst[i] = min(max(dv, 0), N_NODES - 1);
        }
        __syncthreads();

        // ---- stage 1: h = relu(raw @ ew1 + eb1) -> Ah/Al (padded rows) ----
        {
            const int eg1 = tid >> 4;          // 32 groups x 4 edges
            const int cg1 = tid & 15;          // 16 groups x 8 cols (k)
            const int col0 = cg1 * 8;
            float acc[4][8];
#pragma unroll
            for (int i = 0; i < 4; i++)
#pragma unroll
                for (int j = 0; j < 8; j++) acc[i][j] = s_eb1[col0 + j];
#pragma unroll
            for (int k = 0; k < D_RAW; k++) {
                float w[8];
#pragma unroll
                for (int j = 0; j < 8; j++) w[j] = s_ew1[k * D_HID + col0 + j];
#pragma unroll
                for (int i = 0; i < 4; i++) {
                    float r = s_raw[(eg1 * 4 + i) * D_RAW + k];
#pragma unroll
                    for (int j = 0; j < 8; j++) acc[i][j] = fmaf(r, w[j], acc[i][j]);
                }
            }
#pragma unroll
            for (int i = 0; i < 4; i++) {
                const uint32_t rowbase = (uint32_t)(eg1 * 4 + i) * STRIDE_AB;
#pragma unroll
                for (int t = 0; t < 4; t++) {
                    const int k = col0 + 2 * t;
                    float v0 = fmaxf(acc[i][2 * t],     0.f);
                    float v1 = fmaxf(acc[i][2 * t + 1], 0.f);
                    __nv_bfloat16 h0 = __float2bfloat16(v0);
                    __nv_bfloat16 h1 = __float2bfloat16(v1);
                    __nv_bfloat162 ph; ph.x = h0; ph.y = h1;
                    __nv_bfloat162 pl;
                    pl.x = __float2bfloat16(v0 - __bfloat162float(h0));
                    pl.y = __float2bfloat16(v1 - __bfloat162float(h1));
                    uint32_t byte = rowbase + (uint32_t)k * 2u;
                    *(uint32_t*)(smem + OFF_AH + byte) = *(uint32_t*)&ph;
                    *(uint32_t*)(smem + OFF_AL + byte) = *(uint32_t*)&pl;
                }
            }
        }
        __syncthreads();

        // ---- warp MMA: D = Ah@Bh^T + Al@Bh^T + Ah@Bl^T (fp32 accum) ----
        float acc[2][8][4];
#pragma unroll
        for (int ma = 0; ma < 2; ma++)
#pragma unroll
            for (int na = 0; na < 8; na++)
#pragma unroll
                for (int r = 0; r < 4; r++) acc[ma][na][r] = 0.f;

#pragma unroll
        for (int ks = 0; ks < 8; ks++) {
            uint32_t ah0[4], ah1[4], al0[4], al1[4];
            const uint32_t ka = (uint32_t)ks * 32u;
            ldsm_x4(ah0, smem_u + OFF_AH + a_off + ka);
            ldsm_x4(ah1, smem_u + OFF_AH + a_off + 16u * STRIDE_AB + ka);
            ldsm_x4(al0, smem_u + OFF_AL + a_off + ka);
            ldsm_x4(al1, smem_u + OFF_AL + a_off + 16u * STRIDE_AB + ka);
#pragma unroll
            for (int na = 0; na < 8; na++) {
                uint32_t bh[2], bl[2];
                const uint32_t bo = b_off + (uint32_t)na * 8u * STRIDE_AB + ka;
                ldsm_x2(bh, smem_u + OFF_BH + bo);
                ldsm_x2(bl, smem_u + OFF_BL + bo);
                mma_bf16(acc[0][na], ah0, bh);
                mma_bf16(acc[1][na], ah1, bh);
                mma_bf16(acc[0][na], al0, bh);
                mma_bf16(acc[1][na], al1, bh);
                mma_bf16(acc[0][na], ah0, bl);
                mma_bf16(acc[1][na], ah1, bl);
            }
        }

        // ---- epilogue: fragment -> gather x[src] + relu + RED to g_h[dst] --
#pragma unroll
        for (int ma = 0; ma < 2; ma++) {
#pragma unroll
            for (int hl = 0; hl < 2; hl++) {
                const int row = wm * 32 + ma * 16 + q + hl * 8;
                const float s = s_pol[row];
                const float* xr = x + (size_t)s_src[row] * D_IN + wn * 64;
                float* hd = g_h + (size_t)s_dst[row] * D_IN + wn * 64;
#pragma unroll
                for (int na = 0; na < 8; na++) {
                    const int cl = na * 8 + cp;            // 0..63
                    const int col = wn * 64 + cl;          // global col
                    float v0 = acc[ma][na][hl * 2 + 0];
                    float v1 = acc[ma][na][hl * 2 + 1];
                    float2 bb = *(const float2*)&s_b2l[col];
                    float2 ll = *(const float2*)&s_leb[col];
                    float2 xv = *(const float2*)(xr + cl);
                    float m0 = fmaxf(fmaf(s, v0 + bb.x, ll.x) + xv.x, 0.f);
                    float m1 = fmaxf(fmaf(s, v1 + bb.y, ll.y) + xv.y, 0.f);
                    red_v2(hd + cl, m0, m1);
                }
            }
        }
        __syncthreads();
    }
}

// ---------------- K3: h1 = LN(g_h @ w1 + b1); g_t = relu(h1) ---------------
#define ROWS_B 64
__global__ __launch_bounds__(256)
void node1_kernel(const float* __restrict__ w1, const float* __restrict__ b1,
                  const float* __restrict__ ln_g, const float* __restrict__ ln_b) {
    __shared__ float s_a[ROWS_B * 32];
    __shared__ float s_w[32 * D_IN];
    const int tid = threadIdx.x;
    const int r0 = blockIdx.x * ROWS_B;
    const int eg = tid >> 5, cg = tid & 31, col0 = cg * 8;
    unsigned long long acc2[8][4];
#pragma unroll
    for (int i = 0; i < 8; i++)
#pragma unroll
        for (int p = 0; p < 4; p++) acc2[i][p] = 0ull;

    for (int kc = 0; kc < D_IN; kc += 32) {
        for (int i = tid; i < ROWS_B * 32; i += 256) {
            int r = i >> 5, k = i & 31;
            int rr = min(r0 + r, N_NODES - 1);
            s_a[i] = g_h[(size_t)rr * D_IN + kc + k];
        }
        for (int i = tid; i < 32 * D_IN; i += 256) {
            int k = i >> 8, c = i & 255;
            s_w[i] = w1[(size_t)(kc + k) * D_IN + c];
        }
        __syncthreads();
#pragma unroll 4
        for (int k = 0; k < 32; k++) {
            const unsigned long long* wr =
                (const unsigned long long*)&s_w[k * D_IN + col0];
            unsigned long long w0 = wr[0], w1v = wr[1], w2v = wr[2], w3v = wr[3];
#pragma unroll
            for (int i = 0; i < 8; i++) {
                float a = s_a[(eg * 8 + i) * 32 + k];
                unsigned long long a2 = pack2(a, a);
                fma2(acc2[i][0], a2, w0);
                fma2(acc2[i][1], a2, w1v);
                fma2(acc2[i][2], a2, w2v);
                fma2(acc2[i][3], a2, w3v);
            }
        }
        __syncthreads();
    }

    float4 b1a = *(const float4*)&b1[col0];
    float4 b1b = *(const float4*)&b1[col0 + 4];
    float4 ga  = *(const float4*)&ln_g[col0];
    float4 gb  = *(const float4*)&ln_g[col0 + 4];
    float4 ba  = *(const float4*)&ln_b[col0];
    float4 bb  = *(const float4*)&ln_b[col0 + 4];
    const float bv[8] = {b1a.x,b1a.y,b1a.z,b1a.w,b1b.x,b1b.y,b1b.z,b1b.w};
    const float gv[8] = {ga.x,ga.y,ga.z,ga.w,gb.x,gb.y,gb.z,gb.w};
    const float lv[8] = {ba.x,ba.y,ba.z,ba.w,bb.x,bb.y,bb.z,bb.w};

#pragma unroll
    for (int i = 0; i < 8; i++) {
        const int row = r0 + eg * 8 + i;
        float v[8];
#pragma unroll
        for (int p = 0; p < 4; p++) {
            float2 f = unpack2(acc2[i][p]);
            v[2 * p] = f.x; v[2 * p + 1] = f.y;
        }
        float ps = 0.f;
#pragma unroll
        for (int j = 0; j < 8; j++) { v[j] += bv[j]; ps += v[j]; }
#pragma unroll
        for (int m = 16; m >= 1; m >>= 1) ps += __shfl_xor_sync(0xffffffffu, ps, m);
        const float mu = ps * (1.f / D_IN);
        float vs = 0.f;
#pragma unroll
        for (int j = 0; j < 8; j++) { float d = v[j] - mu; vs = fmaf(d, d, vs); }
#pragma unroll
        for (int m = 16; m >= 1; m >>= 1) vs += __shfl_xor_sync(0xffffffffu, vs, m);
        const float rstd = rsqrtf(vs * (1.f / D_IN) + LN_EPS);
        if (row < N_NODES) {
            float o[8];
#pragma unroll
            for (int j = 0; j < 8; j++)
                o[j] = fmaxf(fmaf((v[j] - mu) * rstd, gv[j], lv[j]), 0.f);
            float* dst = g_t + (size_t)row * D_IN + col0;
            *(float4*)dst       = make_float4(o[0], o[1], o[2], o[3]);
            *(float4*)(dst + 4) = make_float4(o[4], o[5], o[6], o[7]);
        }
    }
}

// ---------------- K4: out = g_t @ w2 + b2 ----------------------------------
__global__ __launch_bounds__(256)
void node2_kernel(const float* __restrict__ w2, const float* __restrict__ b2,
                  float* __restrict__ out) {
    __shared__ float s_a[ROWS_B * 32];
    __shared__ float s_w[32 * D_IN];
    const int tid = threadIdx.x;
    const int r0 = blockIdx.x * ROWS_B;
    const int eg = tid >> 5, cg = tid & 31, col0 = cg * 8;
    unsigned long long acc2[8][4];
#pragma unroll
    for (int i = 0; i < 8; i++)
#pragma unroll
        for (int p = 0; p < 4; p++) acc2[i][p] = 0ull;

    for (int kc = 0; kc < D_IN; kc += 32) {
        for (int i = tid; i < ROWS_B * 32; i += 256) {
            int r = i >> 5, k = i & 31;
            int rr = min(r0 + r, N_NODES - 1);
            s_a[i] = g_t[(size_t)rr * D_IN + kc + k];
        }
        for (int i = tid; i < 32 * D_IN; i += 256) {
            int k = i >> 8, c = i & 255;
            s_w[i] = w2[(size_t)(kc + k) * D_IN + c];
        }
        __syncthreads();
#pragma unroll 4
        for (int k = 0; k < 32; k++) {
            const unsigned long long* wr =
                (const unsigned long long*)&s_w[k * D_IN + col0];
            unsigned long long w0 = wr[0], w1v = wr[1], w2v = wr[2], w3v = wr[3];
#pragma unroll
            for (int i = 0; i < 8; i++) {
                float a = s_a[(eg * 8 + i) * 32 + k];
                unsigned long long a2 = pack2(a, a);
                fma2(acc2[i][0], a2, w0);
                fma2(acc2[i][1], a2, w1v);
                fma2(acc2[i][2], a2, w2v);
                fma2(acc2[i][3], a2, w3v);
            }
        }
        __syncthreads();
    }

    float4 b2a = *(const float4*)&b2[col0];
    float4 b2b = *(const float4*)&b2[col0 + 4];
    const float bv[8] = {b2a.x,b2a.y,b2a.z,b2a.w,b2b.x,b2b.y,b2b.z,b2b.w};
#pragma unroll
    for (int i = 0; i < 8; i++) {
        const int row = r0 + eg * 8 + i;
        if (row < N_NODES) {
            float v[8];
#pragma unroll
            for (int p = 0; p < 4; p++) {
                float2 f = unpack2(acc2[i][p]);
                v[2 * p] = f.x + bv[2 * p];
                v[2 * p + 1] = f.y + bv[2 * p + 1];
            }
            float* dst = out + (size_t)row * D_IN + col0;
            *(float4*)dst       = make_float4(v[0], v[1], v[2], v[3]);
            *(float4*)(dst + 4) = make_float4(v[4], v[5], v[6], v[7]);
        }
    }
}

// ---------------- launcher --------------------------------------------------
extern "C" void kernel_launch(void* const* d_in, const int* in_sizes, int n_in,
                              void* d_out, int out_size) {
    const float* x    = (const float*)d_in[0];
    const void*  ei   = d_in[1];
    const float* ea   = (const float*)d_in[2];
    const float* ew1  = (const float*)d_in[3];
    const float* eb1  = (const float*)d_in[4];
    const float* ew2  = (const float*)d_in[5];
    const float* eb2  = (const float*)d_in[6];
    const float* lew  = (const float*)d_in[7];
    const float* leb  = (const float*)d_in[8];
    const float* w1   = (const float*)d_in[9];
    const float* b1   = (const float*)d_in[10];
    const float* ln_g = (const float*)d_in[11];
    const float* ln_b = (const float*)d_in[12];
    const float* w2   = (const float*)d_in[13];
    const float* b2   = (const float*)d_in[14];
    float* out = (float*)d_out;

    cudaFuncSetAttribute(edge_kernel, cudaFuncAttributeMaxDynamicSharedMemorySize,
                         EDGE_SMEM);

    detect_idx_kernel<<<1, 32>>>((const int*)ei);
    precompute_kernel<<<128, 256>>>(ew2, lew, eb2);
    init_h_kernel<<<1184, 256>>>(x);
    edge_kernel<<<148, 512, EDGE_SMEM>>>(x, ei, ea, ew1, eb1, leb);
    node1_kernel<<<(N_NODES + ROWS_B - 1) / ROWS_B, 256>>>(w1, b1, ln_g, ln_b);
    node2_kernel<<<(N_NODES + ROWS_B - 1) / ROWS_B, 256>>>(w2, b2, out);
}

// round 6
// speedup vs baseline: 1.8183x; 1.1539x over previous
#include <cuda_runtime.h>
#include <cuda_bf16.h>
#include <cstdint>

#define N_NODES 50000
#define N_EDGES 800000
#define D_IN    256
#define D_HID   128
#define D_RAW   16
#define TILE_E  128
#define LN_EPS  1e-5f

static_assert(N_EDGES % TILE_E == 0, "edge tiling assumes exact division");

// ---------------- packed f32x2 helpers (node kernels) ----------------------
__device__ __forceinline__ unsigned long long pack2(float lo, float hi) {
    unsigned long long r;
    asm("mov.b64 %0, {%1, %2};" : "=l"(r) : "f"(lo), "f"(hi));
    return r;
}
__device__ __forceinline__ void fma2(unsigned long long& d,
                                     unsigned long long a,
                                     unsigned long long b) {
    asm("fma.rn.f32x2 %0, %1, %2, %0;" : "+l"(d) : "l"(a), "l"(b));
}
__device__ __forceinline__ float2 unpack2(unsigned long long v) {
    float2 f;
    asm("mov.b64 {%0, %1}, %2;" : "=f"(f.x), "=f"(f.y) : "l"(v));
    return f;
}

// ---------------- portable warp-MMA helpers (sm_80+ PTX) -------------------
__device__ __forceinline__ uint32_t smem_to_u32(const void* p) {
    uint32_t a;
    asm("{ .reg .u64 t; cvta.to.shared.u64 t, %1; cvt.u32.u64 %0, t; }"
        : "=r"(a) : "l"(p));
    return a;
}
__device__ __forceinline__ void ldsm_x4(uint32_t* r, uint32_t addr) {
    asm volatile("ldmatrix.sync.aligned.m8n8.x4.shared.b16 {%0,%1,%2,%3}, [%4];"
                 : "=r"(r[0]), "=r"(r[1]), "=r"(r[2]), "=r"(r[3]) : "r"(addr));
}
__device__ __forceinline__ void mma_bf16(float* d, const uint32_t* a,
                                         const uint32_t* b) {
    asm volatile(
        "mma.sync.aligned.m16n8k16.row.col.f32.bf16.bf16.f32 "
        "{%0,%1,%2,%3}, {%4,%5,%6,%7}, {%8,%9}, {%0,%1,%2,%3};"
        : "+f"(d[0]), "+f"(d[1]), "+f"(d[2]), "+f"(d[3])
        : "r"(a[0]), "r"(a[1]), "r"(a[2]), "r"(a[3]), "r"(b[0]), "r"(b[1]));
}
__device__ __forceinline__ void red_v2(float* gptr, float a, float b) {
    asm volatile("red.global.add.v2.f32 [%0], {%1, %2};"
                 :: "l"(gptr), "f"(a), "f"(b) : "memory");
}

// ---------------- scratch (device globals; no runtime allocation) ----------
__device__ float g_b2l[D_IN];                       // eb2 @ lew
__device__ __nv_bfloat16 g_Bh[D_IN * D_HID];        // bf16(W2L^T) [n][k]
__device__ float g_h[(size_t)N_NODES * D_IN];       // x + aggr (atomic target)
__device__ float g_t[(size_t)N_NODES * D_IN];       // relu(LN(h@w1+b1))
__device__ int   g_is64;                            // edge_index dtype flag

// ---------------- K-1: detect edge_index dtype ------------------------------
__global__ void detect_idx_kernel(const int* __restrict__ ei32) {
    if (threadIdx.x == 0 && blockIdx.x == 0) {
        int is64 = 1;
        for (int i = 0; i < 64; i++)
            if (ei32[2 * i + 1] != 0) { is64 = 0; break; }
        g_is64 = is64;
    }
}

// ---------------- K0: fold ew2 @ lew, bf16 hi part --------------------------
__global__ void precompute_kernel(const float* __restrict__ ew2,
                                  const float* __restrict__ lew,
                                  const float* __restrict__ eb2) {
    int idx = blockIdx.x * blockDim.x + threadIdx.x;   // 0..32767
    int k = idx >> 8;      // 0..127 (hid)
    int n = idx & 255;     // 0..255 (out col)
    float s = 0.f;
#pragma unroll 8
    for (int j = 0; j < D_HID; j++)
        s = fmaf(ew2[k * D_HID + j], lew[j * D_IN + n], s);
    g_Bh[n * D_HID + k] = __float2bfloat16(s);
    if (idx < D_IN) {
        float b = 0.f;
        for (int j = 0; j < D_HID; j++)
            b = fmaf(eb2[j], lew[j * D_IN + idx], b);
        g_b2l[idx] = b;
    }
}

// ---------------- K1: g_h = x ----------------------------------------------
__global__ void init_h_kernel(const float* __restrict__ x) {
    const size_t total = (size_t)N_NODES * D_IN / 4;
    const float4* xs = (const float4*)x;
    float4* hs = (float4*)g_h;
    for (size_t i = (size_t)blockIdx.x * blockDim.x + threadIdx.x; i < total;
         i += (size_t)gridDim.x * blockDim.x)
        hs[i] = xs[i];
}

// ---------------- K2: pipelined edge kernel (bf16x2 emulation) --------------
// D = (Ah + Al) @ Bh^T   (error ~1e-4, see round log)
// one __syncthreads per tile; A double-buffered; edges warp-local.
#define STRIDE_AB 272
#define OFF_BH   0          // 256*272 = 69632
#define OFF_A    69632      // 2 bufs x (Ah,Al) x 128*272 = 139264 -> 208896
#define A_BUF_SZ 69632      // one buf = Ah (34816) + Al (34816)
#define A_SPL_SZ 34816
#define OFF_EW1  208896     // 8192
#define OFF_RAW  217088     // 8192 (warp-local rows, single buffer)
#define OFF_EB1  225280     // 512
#define OFF_B2L  225792     // 1024
#define OFF_LEB  226816     // 1024
#define OFF_POL  227840     // 2 x 512
#define OFF_SRC  228864     // 2 x 512
#define OFF_DST  229888     // 2 x 512
#define EDGE_SMEM 230912

__global__ __launch_bounds__(512, 1)
void edge_kernel(const float* __restrict__ x,
                 const void* __restrict__ ei_raw,
                 const float* __restrict__ ea,
                 const float* __restrict__ ew1,
                 const float* __restrict__ eb1,
                 const float* __restrict__ leb) {
    extern __shared__ char smem[];
    const uint32_t smem_u = smem_to_u32(smem);
    float* s_ew1 = (float*)(smem + OFF_EW1);
    float* s_raw = (float*)(smem + OFF_RAW);
    float* s_eb1 = (float*)(smem + OFF_EB1);
    float* s_b2l = (float*)(smem + OFF_B2L);
    float* s_leb = (float*)(smem + OFF_LEB);
    float* s_pol = (float*)(smem + OFF_POL);   // [2][128]
    int*   s_src = (int*)(smem + OFF_SRC);     // [2][128]
    int*   s_dst = (int*)(smem + OFF_DST);     // [2][128]

    const int tid = threadIdx.x;
    const int wid = tid >> 5;
    const int lane = tid & 31;
    const int is64 = g_is64;
    const long long* ei64 = (const long long*)ei_raw;
    const int*       ei32 = (const int*)ei_raw;

    // ---- stage invariants ----
    for (int w = tid; w < 256 * 64; w += 512) {      // B hi, padded rows
        int n = w >> 6, k2 = w & 63;
        *(uint32_t*)(smem + OFF_BH + (uint32_t)n * STRIDE_AB + (uint32_t)k2 * 4u)
            = ((const uint32_t*)g_Bh)[w];
    }
    for (int i = tid; i < D_RAW * D_HID; i += 512) s_ew1[i] = ew1[i];
    if (tid < D_HID) s_eb1[tid] = eb1[tid];
    if (tid < D_IN) { s_b2l[tid] = g_b2l[tid]; s_leb[tid] = leb[tid]; }
    __syncthreads();

    const int numTiles = N_EDGES / TILE_E;
    const int stride = gridDim.x;

    // warp-local producer: load 8 edges + stage1 -> A[buf]
    auto produce = [&](int t, int bb) {
        const int e0 = t * TILE_E;
        const int er0 = wid * 8;                     // my first local edge row
        for (int i = lane; i < 8 * 17; i += 32) {
            int le = i / 17, c = i % 17;
            float v = ea[(size_t)(e0 + er0 + le) * 17 + c];
            if (c == 0)
                s_pol[bb * TILE_E + er0 + le] = fminf(fmaxf(v, 0.f), 1.f) + 0.01f;
            else
                s_raw[(er0 + le) * D_RAW + (c - 1)] = v;
        }
        if (lane < 8) {
            int sv = is64 ? (int)ei64[e0 + er0 + lane] : ei32[e0 + er0 + lane];
            s_src[bb * TILE_E + er0 + lane] = min(max(sv, 0), N_NODES - 1);
        } else if (lane < 16) {
            int l8 = lane - 8;
            int dv = is64 ? (int)ei64[N_EDGES + e0 + er0 + l8]
                          : ei32[N_EDGES + e0 + er0 + l8];
            s_dst[bb * TILE_E + er0 + l8] = min(max(dv, 0), N_NODES - 1);
        }
        __syncwarp();

        const int c0 = lane * 4;                     // 4 hid cols per lane
        float4 a4[8];
        float4 eb4 = *(const float4*)&s_eb1[c0];
#pragma unroll
        for (int e = 0; e < 8; e++) a4[e] = eb4;
#pragma unroll
        for (int kb = 0; kb < 4; kb++) {
            float4 w0 = *(const float4*)&s_ew1[(kb * 4 + 0) * D_HID + c0];
            float4 w1 = *(const float4*)&s_ew1[(kb * 4 + 1) * D_HID + c0];
            float4 w2 = *(const float4*)&s_ew1[(kb * 4 + 2) * D_HID + c0];
            float4 w3 = *(const float4*)&s_ew1[(kb * 4 + 3) * D_HID + c0];
#pragma unroll
            for (int e = 0; e < 8; e++) {
                float4 r = *(const float4*)&s_raw[(er0 + e) * D_RAW + kb * 4];
                float4 a = a4[e];
                a.x = fmaf(r.x, w0.x, a.x); a.y = fmaf(r.x, w0.y, a.y);
                a.z = fmaf(r.x, w0.z, a.z); a.w = fmaf(r.x, w0.w, a.w);
                a.x = fmaf(r.y, w1.x, a.x); a.y = fmaf(r.y, w1.y, a.y);
                a.z = fmaf(r.y, w1.z, a.z); a.w = fmaf(r.y, w1.w, a.w);
                a.x = fmaf(r.z, w2.x, a.x); a.y = fmaf(r.z, w2.y, a.y);
                a.z = fmaf(r.z, w2.z, a.z); a.w = fmaf(r.z, w2.w, a.w);
                a.x = fmaf(r.w, w3.x, a.x); a.y = fmaf(r.w, w3.y, a.y);
                a.z = fmaf(r.w, w3.z, a.z); a.w = fmaf(r.w, w3.w, a.w);
                a4[e] = a;
            }
        }
        char* ah = smem + OFF_A + bb * A_BUF_SZ + (er0 * STRIDE_AB) + lane * 8;
        char* al = ah + A_SPL_SZ;
#pragma unroll
        for (int e = 0; e < 8; e++) {
            float4 a = a4[e];
            float v0 = fmaxf(a.x, 0.f), v1 = fmaxf(a.y, 0.f);
            float v2 = fmaxf(a.z, 0.f), v3 = fmaxf(a.w, 0.f);
            __nv_bfloat162 h01, h23, l01, l23;
            h01.x = __float2bfloat16(v0); h01.y = __float2bfloat16(v1);
            h23.x = __float2bfloat16(v2); h23.y = __float2bfloat16(v3);
            l01.x = __float2bfloat16(v0 - __bfloat162float(h01.x));
            l01.y = __float2bfloat16(v1 - __bfloat162float(h01.y));
            l23.x = __float2bfloat16(v2 - __bfloat162float(h23.x));
            l23.y = __float2bfloat16(v3 - __bfloat162float(h23.y));
            uint2 vh = make_uint2(*(uint32_t*)&h01, *(uint32_t*)&h23);
            uint2 vl = make_uint2(*(uint32_t*)&l01, *(uint32_t*)&l23);
            *(uint2*)(ah + e * STRIDE_AB) = vh;
            *(uint2*)(al + e * STRIDE_AB) = vl;
        }
    };

    // warp tile for MMA: rows [wm*32,+32), cols [wn*64,+64)
    const int wm = wid & 3;
    const int wn = wid >> 2;
    const uint32_t a_off = (uint32_t)(wm * 32 + (lane & 15)) * STRIDE_AB +
                           (uint32_t)(lane >> 4) * 16u;
    const uint32_t b4_off = (uint32_t)(wn * 64 + ((lane >> 4) & 1) * 8 +
                                       (lane & 7)) * STRIDE_AB +
                            (uint32_t)((lane >> 3) & 1) * 16u;
    const int q  = lane >> 2;
    const int cp = (lane & 3) * 2;

    // prologue: produce tile for iteration 0 into buf 0
    produce(blockIdx.x, 0);
    __syncthreads();

    int bufp = 0;
    for (int t = blockIdx.x; t < numTiles; t += stride) {
        const int b = bufp;

        // ---- MMA(t): D = (Ah + Al) @ Bh^T ----
        float acc[2][8][4];
#pragma unroll
        for (int ma = 0; ma < 2; ma++)
#pragma unroll
            for (int na = 0; na < 8; na++)
#pragma unroll
                for (int r = 0; r < 4; r++) acc[ma][na][r] = 0.f;

        const uint32_t aBase = smem_u + OFF_A + b * A_BUF_SZ;
#pragma unroll
        for (int ks = 0; ks < 8; ks++) {
            const uint32_t ka = (uint32_t)ks * 32u;
            uint32_t ah0[4], ah1[4], al0[4], al1[4];
            ldsm_x4(ah0, aBase + a_off + ka);
            ldsm_x4(ah1, aBase + a_off + 16u * STRIDE_AB + ka);
            ldsm_x4(al0, aBase + A_SPL_SZ + a_off + ka);
            ldsm_x4(al1, aBase + A_SPL_SZ + a_off + 16u * STRIDE_AB + ka);
#pragma unroll
            for (int np = 0; np < 4; np++) {
                uint32_t bq[4];
                ldsm_x4(bq, smem_u + OFF_BH + b4_off +
                            (uint32_t)np * 16u * STRIDE_AB + ka);
                mma_bf16(acc[0][2 * np],     ah0, &bq[0]);
                mma_bf16(acc[1][2 * np],     ah1, &bq[0]);
                mma_bf16(acc[0][2 * np],     al0, &bq[0]);
                mma_bf16(acc[1][2 * np],     al1, &bq[0]);
                mma_bf16(acc[0][2 * np + 1], ah0, &bq[2]);
                mma_bf16(acc[1][2 * np + 1], ah1, &bq[2]);
                mma_bf16(acc[0][2 * np + 1], al0, &bq[2]);
                mma_bf16(acc[1][2 * np + 1], al1, &bq[2]);
            }
        }

        // ---- produce(t+stride) into other buffer (overlaps MMA latency) ----
        const int tn = t + stride;
        if (tn < numTiles) produce(tn, b ^ 1);

        // ---- epilogue(t): gather x[src] + relu + RED to g_h[dst] ----
#pragma unroll
        for (int ma = 0; ma < 2; ma++) {
#pragma unroll
            for (int hl = 0; hl < 2; hl++) {
                const int row = wm * 32 + ma * 16 + q + hl * 8;
                const float s = s_pol[b * TILE_E + row];
                const float* xr =
                    x + (size_t)s_src[b * TILE_E + row] * D_IN + wn * 64;
                float* hd =
                    g_h + (size_t)s_dst[b * TILE_E + row] * D_IN + wn * 64;
#pragma unroll
                for (int na = 0; na < 8; na++) {
                    const int cl = na * 8 + cp;
                    const int col = wn * 64 + cl;
                    float v0 = acc[ma][na][hl * 2 + 0];
                    float v1 = acc[ma][na][hl * 2 + 1];
                    float2 bb = *(const float2*)&s_b2l[col];
                    float2 ll = *(const float2*)&s_leb[col];
                    float2 xv = *(const float2*)(xr + cl);
                    float m0 = fmaxf(fmaf(s, v0 + bb.x, ll.x) + xv.x, 0.f);
                    float m1 = fmaxf(fmaf(s, v1 + bb.y, ll.y) + xv.y, 0.f);
                    red_v2(hd + cl, m0, m1);
                }
            }
        }

        bufp ^= 1;
        __syncthreads();
    }
}

// ---------------- K3: h1 = LN(g_h @ w1 + b1); g_t = relu(h1) ---------------
#define ROWS_B 64
__global__ __launch_bounds__(256)
void node1_kernel(const float* __restrict__ w1, const float* __restrict__ b1,
                  const float* __restrict__ ln_g, const float* __restrict__ ln_b) {
    __shared__ float s_a[ROWS_B * 32];
    __shared__ float s_w[32 * D_IN];
    const int tid = threadIdx.x;
    const int r0 = blockIdx.x * ROWS_B;
    const int eg = tid >> 5, cg = tid & 31, col0 = cg * 8;
    unsigned long long acc2[8][4];
#pragma unroll
    for (int i = 0; i < 8; i++)
#pragma unroll
        for (int p = 0; p < 4; p++) acc2[i][p] = 0ull;

    for (int kc = 0; kc < D_IN; kc += 32) {
        for (int i = tid; i < ROWS_B * 32; i += 256) {
            int r = i >> 5, k = i & 31;
            int rr = min(r0 + r, N_NODES - 1);
            s_a[i] = g_h[(size_t)rr * D_IN + kc + k];
        }
        for (int i = tid; i < 32 * D_IN; i += 256) {
            int k = i >> 8, c = i & 255;
            s_w[i] = w1[(size_t)(kc + k) * D_IN + c];
        }
        __syncthreads();
#pragma unroll 4
        for (int k = 0; k < 32; k++) {
            const unsigned long long* wr =
                (const unsigned long long*)&s_w[k * D_IN + col0];
            unsigned long long w0 = wr[0], w1v = wr[1], w2v = wr[2], w3v = wr[3];
#pragma unroll
            for (int i = 0; i < 8; i++) {
                float a = s_a[(eg * 8 + i) * 32 + k];
                unsigned long long a2 = pack2(a, a);
                fma2(acc2[i][0], a2, w0);
                fma2(acc2[i][1], a2, w1v);
                fma2(acc2[i][2], a2, w2v);
                fma2(acc2[i][3], a2, w3v);
            }
        }
        __syncthreads();
    }

    float4 b1a = *(const float4*)&b1[col0];
    float4 b1b = *(const float4*)&b1[col0 + 4];
    float4 ga  = *(const float4*)&ln_g[col0];
    float4 gb  = *(const float4*)&ln_g[col0 + 4];
    float4 ba  = *(const float4*)&ln_b[col0];
    float4 bb  = *(const float4*)&ln_b[col0 + 4];
    const float bv[8] = {b1a.x,b1a.y,b1a.z,b1a.w,b1b.x,b1b.y,b1b.z,b1b.w};
    const float gv[8] = {ga.x,ga.y,ga.z,ga.w,gb.x,gb.y,gb.z,gb.w};
    const float lv[8] = {ba.x,ba.y,ba.z,ba.w,bb.x,bb.y,bb.z,bb.w};

#pragma unroll
    for (int i = 0; i < 8; i++) {
        const int row = r0 + eg * 8 + i;
        float v[8];
#pragma unroll
        for (int p = 0; p < 4; p++) {
            float2 f = unpack2(acc2[i][p]);
            v[2 * p] = f.x; v[2 * p + 1] = f.y;
        }
        float ps = 0.f;
#pragma unroll
        for (int j = 0; j < 8; j++) { v[j] += bv[j]; ps += v[j]; }
#pragma unroll
        for (int m = 16; m >= 1; m >>= 1) ps += __shfl_xor_sync(0xffffffffu, ps, m);
        const float mu = ps * (1.f / D_IN);
        float vs = 0.f;
#pragma unroll
        for (int j = 0; j < 8; j++) { float d = v[j] - mu; vs = fmaf(d, d, vs); }
#pragma unroll
        for (int m = 16; m >= 1; m >>= 1) vs += __shfl_xor_sync(0xffffffffu, vs, m);
        const float rstd = rsqrtf(vs * (1.f / D_IN) + LN_EPS);
        if (row < N_NODES) {
            float o[8];
#pragma unroll
            for (int j = 0; j < 8; j++)
                o[j] = fmaxf(fmaf((v[j] - mu) * rstd, gv[j], lv[j]), 0.f);
            float* dst = g_t + (size_t)row * D_IN + col0;
            *(float4*)dst       = make_float4(o[0], o[1], o[2], o[3]);
            *(float4*)(dst + 4) = make_float4(o[4], o[5], o[6], o[7]);
        }
    }
}

// ---------------- K4: out = g_t @ w2 + b2 ----------------------------------
__global__ __launch_bounds__(256)
void node2_kernel(const float* __restrict__ w2, const float* __restrict__ b2,
                  float* __restrict__ out) {
    __shared__ float s_a[ROWS_B * 32];
    __shared__ float s_w[32 * D_IN];
    const int tid = threadIdx.x;
    const int r0 = blockIdx.x * ROWS_B;
    const int eg = tid >> 5, cg = tid & 31, col0 = cg * 8;
    unsigned long long acc2[8][4];
#pragma unroll
    for (int i = 0; i < 8; i++)
#pragma unroll
        for (int p = 0; p < 4; p++) acc2[i][p] = 0ull;

    for (int kc = 0; kc < D_IN; kc += 32) {
        for (int i = tid; i < ROWS_B * 32; i += 256) {
            int r = i >> 5, k = i & 31;
            int rr = min(r0 + r, N_NODES - 1);
            s_a[i] = g_t[(size_t)rr * D_IN + kc + k];
        }
        for (int i = tid; i < 32 * D_IN; i += 256) {
            int k = i >> 8, c = i & 255;
            s_w[i] = w2[(size_t)(kc + k) * D_IN + c];
        }
        __syncthreads();
#pragma unroll 4
        for (int k = 0; k < 32; k++) {
            const unsigned long long* wr =
                (const unsigned long long*)&s_w[k * D_IN + col0];
            unsigned long long w0 = wr[0], w1v = wr[1], w2v = wr[2], w3v = wr[3];
#pragma unroll
            for (int i = 0; i < 8; i++) {
                float a = s_a[(eg * 8 + i) * 32 + k];
                unsigned long long a2 = pack2(a, a);
                fma2(acc2[i][0], a2, w0);
                fma2(acc2[i][1], a2, w1v);
                fma2(acc2[i][2], a2, w2v);
                fma2(acc2[i][3], a2, w3v);
            }
        }
        __syncthreads();
    }

    float4 b2a = *(const float4*)&b2[col0];
    float4 b2b = *(const float4*)&b2[col0 + 4];
    const float bv[8] = {b2a.x,b2a.y,b2a.z,b2a.w,b2b.x,b2b.y,b2b.z,b2b.w};
#pragma unroll
    for (int i = 0; i < 8; i++) {
        const int row = r0 + eg * 8 + i;
        if (row < N_NODES) {
            float v[8];
#pragma unroll
            for (int p = 0; p < 4; p++) {
                float2 f = unpack2(acc2[i][p]);
                v[2 * p] = f.x + bv[2 * p];
                v[2 * p + 1] = f.y + bv[2 * p + 1];
            }
            float* dst = out + (size_t)row * D_IN + col0;
            *(float4*)dst       = make_float4(v[0], v[1], v[2], v[3]);
            *(float4*)(dst + 4) = make_float4(v[4], v[5], v[6], v[7]);
        }
    }
}

// ---------------- launcher --------------------------------------------------
extern "C" void kernel_launch(void* const* d_in, const int* in_sizes, int n_in,
                              void* d_out, int out_size) {
    const float* x    = (const float*)d_in[0];
    const void*  ei   = d_in[1];
    const float* ea   = (const float*)d_in[2];
    const float* ew1  = (const float*)d_in[3];
    const float* eb1  = (const float*)d_in[4];
    const float* ew2  = (const float*)d_in[5];
    const float* eb2  = (const float*)d_in[6];
    const float* lew  = (const float*)d_in[7];
    const float* leb  = (const float*)d_in[8];
    const float* w1   = (const float*)d_in[9];
    const float* b1   = (const float*)d_in[10];
    const float* ln_g = (const float*)d_in[11];
    const float* ln_b = (const float*)d_in[12];
    const float* w2   = (const float*)d_in[13];
    const float* b2   = (const float*)d_in[14];
    float* out = (float*)d_out;

    cudaFuncSetAttribute(edge_kernel, cudaFuncAttributeMaxDynamicSharedMemorySize,
                         EDGE_SMEM);

    detect_idx_kernel<<<1, 32>>>((const int*)ei);
    precompute_kernel<<<128, 256>>>(ew2, lew, eb2);
    init_h_kernel<<<1184, 256>>>(x);
    edge_kernel<<<148, 512, EDGE_SMEM>>>(x, ei, ea, ew1, eb1, leb);
    node1_kernel<<<(N_NODES + ROWS_B - 1) / ROWS_B, 256>>>(w1, b1, ln_g, ln_b);
    node2_kernel<<<(N_NODES + ROWS_B - 1) / ROWS_B, 256>>>(w2, b2, out);
}

// round 8
// speedup vs baseline: 2.4483x; 1.3465x over previous
#include <cuda_runtime.h>
#include <cuda_bf16.h>
#include <cstdint>

#define N_NODES 50000
#define N_EDGES 800000
#define D_IN    256
#define D_HID   128
#define D_RAW   16
#define TILE_E  128
#define LN_EPS  1e-5f

static_assert(N_EDGES % TILE_E == 0, "edge tiling assumes exact division");

// ---------------- portable warp-MMA helpers (sm_80+ PTX) -------------------
__device__ __forceinline__ uint32_t smem_to_u32(const void* p) {
    uint32_t a;
    asm("{ .reg .u64 t; cvta.to.shared.u64 t, %1; cvt.u32.u64 %0, t; }"
        : "=r"(a) : "l"(p));
    return a;
}
__device__ __forceinline__ void ldsm_x4(uint32_t* r, uint32_t addr) {
    asm volatile("ldmatrix.sync.aligned.m8n8.x4.shared.b16 {%0,%1,%2,%3}, [%4];"
                 : "=r"(r[0]), "=r"(r[1]), "=r"(r[2]), "=r"(r[3]) : "r"(addr));
}
__device__ __forceinline__ void mma_bf16(float* d, const uint32_t* a,
                                         const uint32_t* b) {
    asm volatile(
        "mma.sync.aligned.m16n8k16.row.col.f32.bf16.bf16.f32 "
        "{%0,%1,%2,%3}, {%4,%5,%6,%7}, {%8,%9}, {%0,%1,%2,%3};"
        : "+f"(d[0]), "+f"(d[1]), "+f"(d[2]), "+f"(d[3])
        : "r"(a[0]), "r"(a[1]), "r"(a[2]), "r"(a[3]), "r"(b[0]), "r"(b[1]));
}
__device__ __forceinline__ void red_v2(float* gptr, float a, float b) {
    asm volatile("red.global.add.v2.f32 [%0], {%1, %2};"
                 :: "l"(gptr), "f"(a), "f"(b) : "memory");
}

// ---------------- scratch (device globals; no runtime allocation) ----------
__device__ float g_b2l[D_IN];                                 // eb2 @ lew
__device__ __align__(16) __nv_bfloat16 g_Bh[D_IN * D_HID];    // bf16(W2L^T) [n][k]
__device__ __align__(16) __nv_bfloat16 g_W1h[D_IN * D_IN];    // w1^T hi [n][k]
__device__ __align__(16) __nv_bfloat16 g_W1l[D_IN * D_IN];    // w1^T lo
__device__ __align__(16) __nv_bfloat16 g_W2h[D_IN * D_IN];    // w2^T hi
__device__ __align__(16) __nv_bfloat16 g_W2l[D_IN * D_IN];    // w2^T lo
__device__ float g_h[(size_t)N_NODES * D_IN];                 // x + aggr
__device__ float g_t[(size_t)N_NODES * D_IN];                 // relu(LN(h@w1+b1))
__device__ int   g_is64;                                      // dtype flag

// ---------------- K-1: detect edge_index dtype ------------------------------
__global__ void detect_idx_kernel(const int* __restrict__ ei32) {
    if (threadIdx.x == 0 && blockIdx.x == 0) {
        int is64 = 1;
        for (int i = 0; i < 64; i++)
            if (ei32[2 * i + 1] != 0) { is64 = 0; break; }
        g_is64 = is64;
    }
}

// ---------------- K0a: fold ew2 @ lew, bf16 hi part -------------------------
__global__ void precompute_kernel(const float* __restrict__ ew2,
                                  const float* __restrict__ lew,
                                  const float* __restrict__ eb2) {
    int idx = blockIdx.x * blockDim.x + threadIdx.x;   // 0..32767
    int k = idx >> 8;      // 0..127 (hid)
    int n = idx & 255;     // 0..255 (out col)
    float s = 0.f;
#pragma unroll 8
    for (int j = 0; j < D_HID; j++)
        s = fmaf(ew2[k * D_HID + j], lew[j * D_IN + n], s);
    g_Bh[n * D_HID + k] = __float2bfloat16(s);
    if (idx < D_IN) {
        float b = 0.f;
        for (int j = 0; j < D_HID; j++)
            b = fmaf(eb2[j], lew[j * D_IN + idx], b);
        g_b2l[idx] = b;
    }
}

// ---------------- K0b: transpose + split node weights -----------------------
// which=0 -> g_W1h/g_W1l, which=1 -> g_W2h/g_W2l  (device globals referenced
// INSIDE device code; passing them as host-side kernel args is the R7 bug).
__global__ void split_w_kernel(const float* __restrict__ w, int which) {
    __nv_bfloat16* Wh = which ? g_W2h : g_W1h;
    __nv_bfloat16* Wl = which ? g_W2l : g_W1l;
    int idx = blockIdx.x * blockDim.x + threadIdx.x;   // 0..65535
    int k = idx >> 8, n = idx & 255;
    float v = w[k * D_IN + n];
    __nv_bfloat16 hi = __float2bfloat16(v);
    Wh[n * D_IN + k] = hi;
    Wl[n * D_IN + k] = __float2bfloat16(v - __bfloat162float(hi));
}

// ---------------- K1: g_h = x ----------------------------------------------
__global__ void init_h_kernel(const float* __restrict__ x) {
    const size_t total = (size_t)N_NODES * D_IN / 4;
    const float4* xs = (const float4*)x;
    float4* hs = (float4*)g_h;
    for (size_t i = (size_t)blockIdx.x * blockDim.x + threadIdx.x; i < total;
         i += (size_t)gridDim.x * blockDim.x)
        hs[i] = xs[i];
}

// ---------------- K2: pipelined edge kernel (unchanged, proven R6) ----------
#define STRIDE_AB 272
#define OFF_BH   0
#define OFF_A    69632
#define A_BUF_SZ 69632
#define A_SPL_SZ 34816
#define OFF_EW1  208896
#define OFF_RAW  217088
#define OFF_EB1  225280
#define OFF_B2L  225792
#define OFF_LEB  226816
#define OFF_POL  227840
#define OFF_SRC  228864
#define OFF_DST  229888
#define EDGE_SMEM 230912

__global__ __launch_bounds__(512, 1)
void edge_kernel(const float* __restrict__ x,
                 const void* __restrict__ ei_raw,
                 const float* __restrict__ ea,
                 const float* __restrict__ ew1,
                 const float* __restrict__ eb1,
                 const float* __restrict__ leb) {
    extern __shared__ char smem[];
    const uint32_t smem_u = smem_to_u32(smem);
    float* s_ew1 = (float*)(smem + OFF_EW1);
    float* s_raw = (float*)(smem + OFF_RAW);
    float* s_eb1 = (float*)(smem + OFF_EB1);
    float* s_b2l = (float*)(smem + OFF_B2L);
    float* s_leb = (float*)(smem + OFF_LEB);
    float* s_pol = (float*)(smem + OFF_POL);
    int*   s_src = (int*)(smem + OFF_SRC);
    int*   s_dst = (int*)(smem + OFF_DST);

    const int tid = threadIdx.x;
    const int wid = tid >> 5;
    const int lane = tid & 31;
    const int is64 = g_is64;
    const long long* ei64 = (const long long*)ei_raw;
    const int*       ei32 = (const int*)ei_raw;

    for (int w = tid; w < 256 * 64; w += 512) {
        int n = w >> 6, k2 = w & 63;
        *(uint32_t*)(smem + OFF_BH + (uint32_t)n * STRIDE_AB + (uint32_t)k2 * 4u)
            = ((const uint32_t*)g_Bh)[w];
    }
    for (int i = tid; i < D_RAW * D_HID; i += 512) s_ew1[i] = ew1[i];
    if (tid < D_HID) s_eb1[tid] = eb1[tid];
    if (tid < D_IN) { s_b2l[tid] = g_b2l[tid]; s_leb[tid] = leb[tid]; }
    __syncthreads();

    const int numTiles = N_EDGES / TILE_E;
    const int stride = gridDim.x;

    auto produce = [&](int t, int bb) {
        const int e0 = t * TILE_E;
        const int er0 = wid * 8;
        for (int i = lane; i < 8 * 17; i += 32) {
            int le = i / 17, c = i % 17;
            float v = ea[(size_t)(e0 + er0 + le) * 17 + c];
            if (c == 0)
                s_pol[bb * TILE_E + er0 + le] = fminf(fmaxf(v, 0.f), 1.f) + 0.01f;
            else
                s_raw[(er0 + le) * D_RAW + (c - 1)] = v;
        }
        if (lane < 8) {
            int sv = is64 ? (int)ei64[e0 + er0 + lane] : ei32[e0 + er0 + lane];
            s_src[bb * TILE_E + er0 + lane] = min(max(sv, 0), N_NODES - 1);
        } else if (lane < 16) {
            int l8 = lane - 8;
            int dv = is64 ? (int)ei64[N_EDGES + e0 + er0 + l8]
                          : ei32[N_EDGES + e0 + er0 + l8];
            s_dst[bb * TILE_E + er0 + l8] = min(max(dv, 0), N_NODES - 1);
        }
        __syncwarp();

        const int c0 = lane * 4;
        float4 a4[8];
        float4 eb4 = *(const float4*)&s_eb1[c0];
#pragma unroll
        for (int e = 0; e < 8; e++) a4[e] = eb4;
#pragma unroll
        for (int kb = 0; kb < 4; kb++) {
            float4 w0 = *(const float4*)&s_ew1[(kb * 4 + 0) * D_HID + c0];
            float4 w1 = *(const float4*)&s_ew1[(kb * 4 + 1) * D_HID + c0];
            float4 w2 = *(const float4*)&s_ew1[(kb * 4 + 2) * D_HID + c0];
            float4 w3 = *(const float4*)&s_ew1[(kb * 4 + 3) * D_HID + c0];
#pragma unroll
            for (int e = 0; e < 8; e++) {
                float4 r = *(const float4*)&s_raw[(er0 + e) * D_RAW + kb * 4];
                float4 a = a4[e];
                a.x = fmaf(r.x, w0.x, a.x); a.y = fmaf(r.x, w0.y, a.y);
                a.z = fmaf(r.x, w0.z, a.z); a.w = fmaf(r.x, w0.w, a.w);
                a.x = fmaf(r.y, w1.x, a.x); a.y = fmaf(r.y, w1.y, a.y);
                a.z = fmaf(r.y, w1.z, a.z); a.w = fmaf(r.y, w1.w, a.w);
                a.x = fmaf(r.z, w2.x, a.x); a.y = fmaf(r.z, w2.y, a.y);
                a.z = fmaf(r.z, w2.z, a.z); a.w = fmaf(r.z, w2.w, a.w);
                a.x = fmaf(r.w, w3.x, a.x); a.y = fmaf(r.w, w3.y, a.y);
                a.z = fmaf(r.w, w3.z, a.z); a.w = fmaf(r.w, w3.w, a.w);
                a4[e] = a;
            }
        }
        char* ah = smem + OFF_A + bb * A_BUF_SZ + (er0 * STRIDE_AB) + lane * 8;
        char* al = ah + A_SPL_SZ;
#pragma unroll
        for (int e = 0; e < 8; e++) {
            float4 a = a4[e];
            float v0 = fmaxf(a.x, 0.f), v1 = fmaxf(a.y, 0.f);
            float v2 = fmaxf(a.z, 0.f), v3 = fmaxf(a.w, 0.f);
            __nv_bfloat162 h01, h23, l01, l23;
            h01.x = __float2bfloat16(v0); h01.y = __float2bfloat16(v1);
            h23.x = __float2bfloat16(v2); h23.y = __float2bfloat16(v3);
            l01.x = __float2bfloat16(v0 - __bfloat162float(h01.x));
            l01.y = __float2bfloat16(v1 - __bfloat162float(h01.y));
            l23.x = __float2bfloat16(v2 - __bfloat162float(h23.x));
            l23.y = __float2bfloat16(v3 - __bfloat162float(h23.y));
            uint2 vh = make_uint2(*(uint32_t*)&h01, *(uint32_t*)&h23);
            uint2 vl = make_uint2(*(uint32_t*)&l01, *(uint32_t*)&l23);
            *(uint2*)(ah + e * STRIDE_AB) = vh;
            *(uint2*)(al + e * STRIDE_AB) = vl;
        }
    };

    const int wm = wid & 3;
    const int wn = wid >> 2;
    const uint32_t a_off = (uint32_t)(wm * 32 + (lane & 15)) * STRIDE_AB +
                           (uint32_t)(lane >> 4) * 16u;
    const uint32_t b4_off = (uint32_t)(wn * 64 + ((lane >> 4) & 1) * 8 +
                                       (lane & 7)) * STRIDE_AB +
                            (uint32_t)((lane >> 3) & 1) * 16u;
    const int q  = lane >> 2;
    const int cp = (lane & 3) * 2;

    produce(blockIdx.x, 0);
    __syncthreads();

    int bufp = 0;
    for (int t = blockIdx.x; t < numTiles; t += stride) {
        const int b = bufp;

        float acc[2][8][4];
#pragma unroll
        for (int ma = 0; ma < 2; ma++)
#pragma unroll
            for (int na = 0; na < 8; na++)
#pragma unroll
                for (int r = 0; r < 4; r++) acc[ma][na][r] = 0.f;

        const uint32_t aBase = smem_u + OFF_A + b * A_BUF_SZ;
#pragma unroll
        for (int ks = 0; ks < 8; ks++) {
            const uint32_t ka = (uint32_t)ks * 32u;
            uint32_t ah0[4], ah1[4], al0[4], al1[4];
            ldsm_x4(ah0, aBase + a_off + ka);
            ldsm_x4(ah1, aBase + a_off + 16u * STRIDE_AB + ka);
            ldsm_x4(al0, aBase + A_SPL_SZ + a_off + ka);
            ldsm_x4(al1, aBase + A_SPL_SZ + a_off + 16u * STRIDE_AB + ka);
#pragma unroll
            for (int np = 0; np < 4; np++) {
                uint32_t bq[4];
                ldsm_x4(bq, smem_u + OFF_BH + b4_off +
                            (uint32_t)np * 16u * STRIDE_AB + ka);
                mma_bf16(acc[0][2 * np],     ah0, &bq[0]);
                mma_bf16(acc[1][2 * np],     ah1, &bq[0]);
                mma_bf16(acc[0][2 * np],     al0, &bq[0]);
                mma_bf16(acc[1][2 * np],     al1, &bq[0]);
                mma_bf16(acc[0][2 * np + 1], ah0, &bq[2]);
                mma_bf16(acc[1][2 * np + 1], ah1, &bq[2]);
                mma_bf16(acc[0][2 * np + 1], al0, &bq[2]);
                mma_bf16(acc[1][2 * np + 1], al1, &bq[2]);
            }
        }

        const int tn = t + stride;
        if (tn < numTiles) produce(tn, b ^ 1);

#pragma unroll
        for (int ma = 0; ma < 2; ma++) {
#pragma unroll
            for (int hl = 0; hl < 2; hl++) {
                const int row = wm * 32 + ma * 16 + q + hl * 8;
                const float s = s_pol[b * TILE_E + row];
                const float* xr =
                    x + (size_t)s_src[b * TILE_E + row] * D_IN + wn * 64;
                float* hd =
                    g_h + (size_t)s_dst[b * TILE_E + row] * D_IN + wn * 64;
#pragma unroll
                for (int na = 0; na < 8; na++) {
                    const int cl = na * 8 + cp;
                    const int col = wn * 64 + cl;
                    float v0 = acc[ma][na][hl * 2 + 0];
                    float v1 = acc[ma][na][hl * 2 + 1];
                    float2 bb = *(const float2*)&s_b2l[col];
                    float2 ll = *(const float2*)&s_leb[col];
                    float2 xv = *(const float2*)(xr + cl);
                    float m0 = fmaxf(fmaf(s, v0 + bb.x, ll.x) + xv.x, 0.f);
                    float m1 = fmaxf(fmaf(s, v1 + bb.y, ll.y) + xv.y, 0.f);
                    red_v2(hd + cl, m0, m1);
                }
            }
        }

        bufp ^= 1;
        __syncthreads();
    }
}

// ---------------- node GEMM kernels (HMMA, 3-term bf16 emulation) ----------
#define NOFF_BH   0          // B hi chunk [256n][272B]
#define NOFF_BL   69632
#define NOFF_AH   139264     // A hi chunk [128m][272B]
#define NOFF_AL   174080
#define NOFF_PART 208896     // [128][4][2] f32 partial sums (node1 LN)
#define NOFF_B    212992     // bias 256 f
#define NOFF_LNG  214016
#define NOFF_LNB  215040
#define NODE_SMEM 216064
#define N_TILES_M ((N_NODES + 127) / 128)   // 391

template <bool WITH_LN>
__device__ __forceinline__ void node_gemm_body(
    const float* __restrict__ Asrc, const __nv_bfloat16* __restrict__ Wh,
    const __nv_bfloat16* __restrict__ Wl, const float* __restrict__ bias,
    const float* __restrict__ ln_g, const float* __restrict__ ln_b,
    float* __restrict__ Dst) {
    extern __shared__ char smem[];
    const uint32_t smem_u = smem_to_u32(smem);
    float* s_part = (float*)(smem + NOFF_PART);
    float* s_b    = (float*)(smem + NOFF_B);
    float* s_lng  = (float*)(smem + NOFF_LNG);
    float* s_lnb  = (float*)(smem + NOFF_LNB);

    const int tid = threadIdx.x;
    const int wid = tid >> 5;
    const int lane = tid & 31;
    const int r0 = blockIdx.x * 128;

    if (tid < D_IN) {
        s_b[tid] = bias[tid];
        if (WITH_LN) { s_lng[tid] = ln_g[tid]; s_lnb[tid] = ln_b[tid]; }
    }

    const int wm = wid & 3;
    const int wn = wid >> 2;
    const uint32_t a_off = (uint32_t)(wm * 32 + (lane & 15)) * STRIDE_AB +
                           (uint32_t)(lane >> 4) * 16u;
    const uint32_t b4_off = (uint32_t)(wn * 64 + ((lane >> 4) & 1) * 8 +
                                       (lane & 7)) * STRIDE_AB +
                            (uint32_t)((lane >> 3) & 1) * 16u;
    const int q  = lane >> 2;
    const int cp = (lane & 3) * 2;

    float acc[2][8][4];
#pragma unroll
    for (int ma = 0; ma < 2; ma++)
#pragma unroll
        for (int na = 0; na < 8; na++)
#pragma unroll
            for (int r = 0; r < 4; r++) acc[ma][na][r] = 0.f;

    for (int kc = 0; kc < 2; kc++) {
        for (int i = tid; i < 256 * 16; i += 512) {
            int n = i >> 4, c = i & 15;
            const size_t src = (size_t)n * D_IN + kc * 128 + c * 8;
            *(uint4*)(smem + NOFF_BH + (uint32_t)n * STRIDE_AB + c * 16) =
                *(const uint4*)(Wh + src);
            *(uint4*)(smem + NOFF_BL + (uint32_t)n * STRIDE_AB + c * 16) =
                *(const uint4*)(Wl + src);
        }
        for (int i = tid; i < 128 * 32; i += 512) {
            int r = i >> 5, c4 = i & 31;
            int rr = min(r0 + r, N_NODES - 1);
            float4 v = *(const float4*)&Asrc[(size_t)rr * D_IN + kc * 128 + c4 * 4];
            __nv_bfloat162 h01, h23, l01, l23;
            h01.x = __float2bfloat16(v.x); h01.y = __float2bfloat16(v.y);
            h23.x = __float2bfloat16(v.z); h23.y = __float2bfloat16(v.w);
            l01.x = __float2bfloat16(v.x - __bfloat162float(h01.x));
            l01.y = __float2bfloat16(v.y - __bfloat162float(h01.y));
            l23.x = __float2bfloat16(v.z - __bfloat162float(h23.x));
            l23.y = __float2bfloat16(v.w - __bfloat162float(h23.y));
            uint32_t off = (uint32_t)r * STRIDE_AB + c4 * 8;
            *(uint2*)(smem + NOFF_AH + off) =
                make_uint2(*(uint32_t*)&h01, *(uint32_t*)&h23);
            *(uint2*)(smem + NOFF_AL + off) =
                make_uint2(*(uint32_t*)&l01, *(uint32_t*)&l23);
        }
        __syncthreads();

#pragma unroll
        for (int ks = 0; ks < 8; ks++) {
            const uint32_t ka = (uint32_t)ks * 32u;
            uint32_t ah0[4], ah1[4], al0[4], al1[4];
            ldsm_x4(ah0, smem_u + NOFF_AH + a_off + ka);
            ldsm_x4(ah1, smem_u + NOFF_AH + a_off + 16u * STRIDE_AB + ka);
            ldsm_x4(al0, smem_u + NOFF_AL + a_off + ka);
            ldsm_x4(al1, smem_u + NOFF_AL + a_off + 16u * STRIDE_AB + ka);
#pragma unroll
            for (int np = 0; np < 4; np++) {
                uint32_t bh[4], bl[4];
                const uint32_t bo = b4_off + (uint32_t)np * 16u * STRIDE_AB + ka;
                ldsm_x4(bh, smem_u + NOFF_BH + bo);
                ldsm_x4(bl, smem_u + NOFF_BL + bo);
                mma_bf16(acc[0][2 * np],     ah0, &bh[0]);
                mma_bf16(acc[1][2 * np],     ah1, &bh[0]);
                mma_bf16(acc[0][2 * np],     al0, &bh[0]);
                mma_bf16(acc[1][2 * np],     al1, &bh[0]);
                mma_bf16(acc[0][2 * np],     ah0, &bl[0]);
                mma_bf16(acc[1][2 * np],     ah1, &bl[0]);
                mma_bf16(acc[0][2 * np + 1], ah0, &bh[2]);
                mma_bf16(acc[1][2 * np + 1], ah1, &bh[2]);
                mma_bf16(acc[0][2 * np + 1], al0, &bh[2]);
                mma_bf16(acc[1][2 * np + 1], al1, &bh[2]);
                mma_bf16(acc[0][2 * np + 1], ah0, &bl[2]);
                mma_bf16(acc[1][2 * np + 1], ah1, &bl[2]);
            }
        }
        __syncthreads();
    }

    float bcol[8][2];
#pragma unroll
    for (int na = 0; na < 8; na++) {
        bcol[na][0] = s_b[wn * 64 + na * 8 + cp];
        bcol[na][1] = s_b[wn * 64 + na * 8 + cp + 1];
    }
#pragma unroll
    for (int ma = 0; ma < 2; ma++)
#pragma unroll
        for (int na = 0; na < 8; na++)
#pragma unroll
            for (int hl = 0; hl < 2; hl++) {
                acc[ma][na][hl * 2 + 0] += bcol[na][0];
                acc[ma][na][hl * 2 + 1] += bcol[na][1];
            }

    if (WITH_LN) {
#pragma unroll
        for (int ma = 0; ma < 2; ma++)
#pragma unroll
            for (int hl = 0; hl < 2; hl++) {
                float s = 0.f, ss = 0.f;
#pragma unroll
                for (int na = 0; na < 8; na++) {
                    float v0 = acc[ma][na][hl * 2 + 0];
                    float v1 = acc[ma][na][hl * 2 + 1];
                    s += v0 + v1;
                    ss = fmaf(v0, v0, ss); ss = fmaf(v1, v1, ss);
                }
                s  += __shfl_xor_sync(0xffffffffu, s, 1);
                s  += __shfl_xor_sync(0xffffffffu, s, 2);
                ss += __shfl_xor_sync(0xffffffffu, ss, 1);
                ss += __shfl_xor_sync(0xffffffffu, ss, 2);
                if ((lane & 3) == 0) {
                    const int row = wm * 32 + ma * 16 + hl * 8 + q;
                    *(float2*)&s_part[row * 8 + wn * 2] = make_float2(s, ss);
                }
            }
        __syncthreads();

#pragma unroll
        for (int ma = 0; ma < 2; ma++)
#pragma unroll
            for (int hl = 0; hl < 2; hl++) {
                const int row = wm * 32 + ma * 16 + hl * 8 + q;
                float sum = 0.f, ssum = 0.f;
#pragma unroll
                for (int w = 0; w < 4; w++) {
                    float2 p = *(const float2*)&s_part[row * 8 + w * 2];
                    sum += p.x; ssum += p.y;
                }
                const float mu = sum * (1.f / D_IN);
                const float var =
                    fmaxf(ssum * (1.f / D_IN) - mu * mu, 0.f);
                const float rstd = rsqrtf(var + LN_EPS);
                const int grow = r0 + row;
                if (grow < N_NODES) {
#pragma unroll
                    for (int na = 0; na < 8; na++) {
                        const int col = wn * 64 + na * 8 + cp;
                        float g0 = s_lng[col], g1 = s_lng[col + 1];
                        float l0 = s_lnb[col], l1 = s_lnb[col + 1];
                        float o0 = fmaxf(
                            fmaf((acc[ma][na][hl * 2] - mu) * rstd, g0, l0), 0.f);
                        float o1 = fmaxf(
                            fmaf((acc[ma][na][hl * 2 + 1] - mu) * rstd, g1, l1),
                            0.f);
                        *(float2*)&Dst[(size_t)grow * D_IN + col] =
                            make_float2(o0, o1);
                    }
                }
            }
    } else {
#pragma unroll
        for (int ma = 0; ma < 2; ma++)
#pragma unroll
            for (int hl = 0; hl < 2; hl++) {
                const int row = wm * 32 + ma * 16 + hl * 8 + q;
                const int grow = r0 + row;
                if (grow < N_NODES) {
#pragma unroll
                    for (int na = 0; na < 8; na++) {
                        const int col = wn * 64 + na * 8 + cp;
                        *(float2*)&Dst[(size_t)grow * D_IN + col] =
                            make_float2(acc[ma][na][hl * 2],
                                        acc[ma][na][hl * 2 + 1]);
                    }
                }
            }
    }
}

__global__ __launch_bounds__(512, 1)
void node1_kernel(const float* __restrict__ b1, const float* __restrict__ ln_g,
                  const float* __restrict__ ln_b) {
    node_gemm_body<true>(g_h, g_W1h, g_W1l, b1, ln_g, ln_b, g_t);
}

__global__ __launch_bounds__(512, 1)
void node2_kernel(const float* __restrict__ b2, float* __restrict__ out) {
    node_gemm_body<false>(g_t, g_W2h, g_W2l, b2, nullptr, nullptr, out);
}

// ---------------- launcher --------------------------------------------------
extern "C" void kernel_launch(void* const* d_in, const int* in_sizes, int n_in,
                              void* d_out, int out_size) {
    const float* x    = (const float*)d_in[0];
    const void*  ei   = d_in[1];
    const float* ea   = (const float*)d_in[2];
    const float* ew1  = (const float*)d_in[3];
    const float* eb1  = (const float*)d_in[4];
    const float* ew2  = (const float*)d_in[5];
    const float* eb2  = (const float*)d_in[6];
    const float* lew  = (const float*)d_in[7];
    const float* leb  = (const float*)d_in[8];
    const float* w1   = (const float*)d_in[9];
    const float* b1   = (const float*)d_in[10];
    const float* ln_g = (const float*)d_in[11];
    const float* ln_b = (const float*)d_in[12];
    const float* w2   = (const float*)d_in[13];
    const float* b2   = (const float*)d_in[14];
    float* out = (float*)d_out;

    cudaFuncSetAttribute(edge_kernel, cudaFuncAttributeMaxDynamicSharedMemorySize,
                         EDGE_SMEM);
    cudaFuncSetAttribute(node1_kernel, cudaFuncAttributeMaxDynamicSharedMemorySize,
                         NODE_SMEM);
    cudaFuncSetAttribute(node2_kernel, cudaFuncAttributeMaxDynamicSharedMemorySize,
                         NODE_SMEM);

    detect_idx_kernel<<<1, 32>>>((const int*)ei);
    precompute_kernel<<<128, 256>>>(ew2, lew, eb2);
    split_w_kernel<<<256, 256>>>(w1, 0);
    split_w_kernel<<<256, 256>>>(w2, 1);
    init_h_kernel<<<1184, 256>>>(x);
    edge_kernel<<<148, 512, EDGE_SMEM>>>(x, ei, ea, ew1, eb1, leb);
    node1_kernel<<<N_TILES_M, 512, NODE_SMEM>>>(b1, ln_g, ln_b);
    node2_kernel<<<N_TILES_M, 512, NODE_SMEM>>>(b2, out);
}

// round 9
// speedup vs baseline: 2.6554x; 1.0846x over previous
#include <cuda_runtime.h>
#include <cuda_bf16.h>
#include <cstdint>

#define N_NODES 50000
#define N_EDGES 800000
#define D_IN    256
#define D_HID   128
#define D_RAW   16
#define TILE_E  128
#define LN_EPS  1e-5f

static_assert(N_EDGES % TILE_E == 0, "edge tiling assumes exact division");

// ---------------- portable warp-MMA helpers (sm_80+ PTX) -------------------
__device__ __forceinline__ uint32_t smem_to_u32(const void* p) {
    uint32_t a;
    asm("{ .reg .u64 t; cvta.to.shared.u64 t, %1; cvt.u32.u64 %0, t; }"
        : "=r"(a) : "l"(p));
    return a;
}
__device__ __forceinline__ void ldsm_x4(uint32_t* r, uint32_t addr) {
    asm volatile("ldmatrix.sync.aligned.m8n8.x4.shared.b16 {%0,%1,%2,%3}, [%4];"
                 : "=r"(r[0]), "=r"(r[1]), "=r"(r[2]), "=r"(r[3]) : "r"(addr));
}
__device__ __forceinline__ void mma_bf16(float* d, const uint32_t* a,
                                         const uint32_t* b) {
    asm volatile(
        "mma.sync.aligned.m16n8k16.row.col.f32.bf16.bf16.f32 "
        "{%0,%1,%2,%3}, {%4,%5,%6,%7}, {%8,%9}, {%0,%1,%2,%3};"
        : "+f"(d[0]), "+f"(d[1]), "+f"(d[2]), "+f"(d[3])
        : "r"(a[0]), "r"(a[1]), "r"(a[2]), "r"(a[3]), "r"(b[0]), "r"(b[1]));
}
__device__ __forceinline__ void red_v2(float* gptr, float a, float b) {
    asm volatile("red.global.add.v2.f32 [%0], {%1, %2};"
                 :: "l"(gptr), "f"(a), "f"(b) : "memory");
}

// ---------------- scratch (device globals; no runtime allocation) ----------
__device__ float g_b2l[D_IN];                                 // eb2 @ lew
__device__ __align__(16) __nv_bfloat16 g_Bh[D_IN * D_HID];    // bf16(W2L^T) [n][k]
__device__ __align__(16) __nv_bfloat16 g_W1h[D_IN * D_IN];    // w1^T hi [n][k]
__device__ __align__(16) __nv_bfloat16 g_W1l[D_IN * D_IN];    // w1^T lo
__device__ __align__(16) __nv_bfloat16 g_W2h[D_IN * D_IN];    // w2^T hi
__device__ __align__(16) __nv_bfloat16 g_W2l[D_IN * D_IN];    // w2^T lo
__device__ float g_h[(size_t)N_NODES * D_IN];                 // x + aggr
__device__ float g_t[(size_t)N_NODES * D_IN];                 // relu(LN(h@w1+b1))
__device__ int   g_is64;                                      // dtype flag

// ---------------- K-1: detect edge_index dtype ------------------------------
__global__ void detect_idx_kernel(const int* __restrict__ ei32) {
    if (threadIdx.x == 0 && blockIdx.x == 0) {
        int is64 = 1;
        for (int i = 0; i < 64; i++)
            if (ei32[2 * i + 1] != 0) { is64 = 0; break; }
        g_is64 = is64;
    }
}

// ---------------- K0a: fold ew2 @ lew, bf16 hi part -------------------------
__global__ void precompute_kernel(const float* __restrict__ ew2,
                                  const float* __restrict__ lew,
                                  const float* __restrict__ eb2) {
    int idx = blockIdx.x * blockDim.x + threadIdx.x;   // 0..32767
    int k = idx >> 8;      // 0..127 (hid)
    int n = idx & 255;     // 0..255 (out col)
    float s = 0.f;
#pragma unroll 8
    for (int j = 0; j < D_HID; j++)
        s = fmaf(ew2[k * D_HID + j], lew[j * D_IN + n], s);
    g_Bh[n * D_HID + k] = __float2bfloat16(s);
    if (idx < D_IN) {
        float b = 0.f;
        for (int j = 0; j < D_HID; j++)
            b = fmaf(eb2[j], lew[j * D_IN + idx], b);
        g_b2l[idx] = b;
    }
}

// ---------------- K0b: transpose + split node weights -----------------------
__global__ void split_w_kernel(const float* __restrict__ w, int which) {
    __nv_bfloat16* Wh = which ? g_W2h : g_W1h;
    __nv_bfloat16* Wl = which ? g_W2l : g_W1l;
    int idx = blockIdx.x * blockDim.x + threadIdx.x;   // 0..65535
    int k = idx >> 8, n = idx & 255;
    float v = w[k * D_IN + n];
    __nv_bfloat16 hi = __float2bfloat16(v);
    Wh[n * D_IN + k] = hi;
    Wl[n * D_IN + k] = __float2bfloat16(v - __bfloat162float(hi));
}

// ---------------- K1: g_h = x ----------------------------------------------
__global__ void init_h_kernel(const float* __restrict__ x) {
    const size_t total = (size_t)N_NODES * D_IN / 4;
    const float4* xs = (const float4*)x;
    float4* hs = (float4*)g_h;
    for (size_t i = (size_t)blockIdx.x * blockDim.x + threadIdx.x; i < total;
         i += (size_t)gridDim.x * blockDim.x)
        hs[i] = xs[i];
}

// ---------------- K2: pipelined edge kernel (1-term bf16: Ah @ Bh^T) --------
#define STRIDE_AB 272
#define OFF_BH   0          // 256*272 = 69632
#define OFF_A    69632      // 2 bufs x 128*272 = 69632 (hi split only)
#define A_BUF_SZ 34816
#define OFF_EW1  139264     // 8192
#define OFF_RAW  147456     // 8192
#define OFF_EB1  155648     // 512
#define OFF_B2L  156160     // 1024
#define OFF_LEB  157184     // 1024
#define OFF_POL  158208     // 2 x 512
#define OFF_SRC  159232     // 2 x 512
#define OFF_DST  160256     // 2 x 512
#define EDGE_SMEM 161280

__global__ __launch_bounds__(512, 1)
void edge_kernel(const float* __restrict__ x,
                 const void* __restrict__ ei_raw,
                 const float* __restrict__ ea,
                 const float* __restrict__ ew1,
                 const float* __restrict__ eb1,
                 const float* __restrict__ leb) {
    extern __shared__ char smem[];
    const uint32_t smem_u = smem_to_u32(smem);
    float* s_ew1 = (float*)(smem + OFF_EW1);
    float* s_raw = (float*)(smem + OFF_RAW);
    float* s_eb1 = (float*)(smem + OFF_EB1);
    float* s_b2l = (float*)(smem + OFF_B2L);
    float* s_leb = (float*)(smem + OFF_LEB);
    float* s_pol = (float*)(smem + OFF_POL);
    int*   s_src = (int*)(smem + OFF_SRC);
    int*   s_dst = (int*)(smem + OFF_DST);

    const int tid = threadIdx.x;
    const int wid = tid >> 5;
    const int lane = tid & 31;
    const int is64 = g_is64;
    const long long* ei64 = (const long long*)ei_raw;
    const int*       ei32 = (const int*)ei_raw;

    for (int w = tid; w < 256 * 64; w += 512) {
        int n = w >> 6, k2 = w & 63;
        *(uint32_t*)(smem + OFF_BH + (uint32_t)n * STRIDE_AB + (uint32_t)k2 * 4u)
            = ((const uint32_t*)g_Bh)[w];
    }
    for (int i = tid; i < D_RAW * D_HID; i += 512) s_ew1[i] = ew1[i];
    if (tid < D_HID) s_eb1[tid] = eb1[tid];
    if (tid < D_IN) { s_b2l[tid] = g_b2l[tid]; s_leb[tid] = leb[tid]; }
    __syncthreads();

    const int numTiles = N_EDGES / TILE_E;
    const int stride = gridDim.x;

    // warp-local producer: load 8 edges + stage1 -> A[buf] (hi split only)
    auto produce = [&](int t, int bb) {
        const int e0 = t * TILE_E;
        const int er0 = wid * 8;
        for (int i = lane; i < 8 * 17; i += 32) {
            int le = i / 17, c = i % 17;
            float v = ea[(size_t)(e0 + er0 + le) * 17 + c];
            if (c == 0)
                s_pol[bb * TILE_E + er0 + le] = fminf(fmaxf(v, 0.f), 1.f) + 0.01f;
            else
                s_raw[(er0 + le) * D_RAW + (c - 1)] = v;
        }
        if (lane < 8) {
            int sv = is64 ? (int)ei64[e0 + er0 + lane] : ei32[e0 + er0 + lane];
            s_src[bb * TILE_E + er0 + lane] = min(max(sv, 0), N_NODES - 1);
        } else if (lane < 16) {
            int l8 = lane - 8;
            int dv = is64 ? (int)ei64[N_EDGES + e0 + er0 + l8]
                          : ei32[N_EDGES + e0 + er0 + l8];
            s_dst[bb * TILE_E + er0 + l8] = min(max(dv, 0), N_NODES - 1);
        }
        __syncwarp();

        const int c0 = lane * 4;
        float4 a4[8];
        float4 eb4 = *(const float4*)&s_eb1[c0];
#pragma unroll
        for (int e = 0; e < 8; e++) a4[e] = eb4;
#pragma unroll
        for (int kb = 0; kb < 4; kb++) {
            float4 w0 = *(const float4*)&s_ew1[(kb * 4 + 0) * D_HID + c0];
            float4 w1 = *(const float4*)&s_ew1[(kb * 4 + 1) * D_HID + c0];
            float4 w2 = *(const float4*)&s_ew1[(kb * 4 + 2) * D_HID + c0];
            float4 w3 = *(const float4*)&s_ew1[(kb * 4 + 3) * D_HID + c0];
#pragma unroll
            for (int e = 0; e < 8; e++) {
                float4 r = *(const float4*)&s_raw[(er0 + e) * D_RAW + kb * 4];
                float4 a = a4[e];
                a.x = fmaf(r.x, w0.x, a.x); a.y = fmaf(r.x, w0.y, a.y);
                a.z = fmaf(r.x, w0.z, a.z); a.w = fmaf(r.x, w0.w, a.w);
                a.x = fmaf(r.y, w1.x, a.x); a.y = fmaf(r.y, w1.y, a.y);
                a.z = fmaf(r.y, w1.z, a.z); a.w = fmaf(r.y, w1.w, a.w);
                a.x = fmaf(r.z, w2.x, a.x); a.y = fmaf(r.z, w2.y, a.y);
                a.z = fmaf(r.z, w2.z, a.z); a.w = fmaf(r.z, w2.w, a.w);
                a.x = fmaf(r.w, w3.x, a.x); a.y = fmaf(r.w, w3.y, a.y);
                a.z = fmaf(r.w, w3.z, a.z); a.w = fmaf(r.w, w3.w, a.w);
                a4[e] = a;
            }
        }
        char* ah = smem + OFF_A + bb * A_BUF_SZ + (er0 * STRIDE_AB) + lane * 8;
#pragma unroll
        for (int e = 0; e < 8; e++) {
            float4 a = a4[e];
            __nv_bfloat162 h01, h23;
            h01.x = __float2bfloat16(fmaxf(a.x, 0.f));
            h01.y = __float2bfloat16(fmaxf(a.y, 0.f));
            h23.x = __float2bfloat16(fmaxf(a.z, 0.f));
            h23.y = __float2bfloat16(fmaxf(a.w, 0.f));
            *(uint2*)(ah + e * STRIDE_AB) =
                make_uint2(*(uint32_t*)&h01, *(uint32_t*)&h23);
        }
    };

    const int wm = wid & 3;
    const int wn = wid >> 2;
    const uint32_t a_off = (uint32_t)(wm * 32 + (lane & 15)) * STRIDE_AB +
                           (uint32_t)(lane >> 4) * 16u;
    const uint32_t b4_off = (uint32_t)(wn * 64 + ((lane >> 4) & 1) * 8 +
                                       (lane & 7)) * STRIDE_AB +
                            (uint32_t)((lane >> 3) & 1) * 16u;
    const int q  = lane >> 2;
    const int cp = (lane & 3) * 2;

    produce(blockIdx.x, 0);
    __syncthreads();

    int bufp = 0;
    for (int t = blockIdx.x; t < numTiles; t += stride) {
        const int b = bufp;

        float acc[2][8][4];
#pragma unroll
        for (int ma = 0; ma < 2; ma++)
#pragma unroll
            for (int na = 0; na < 8; na++)
#pragma unroll
                for (int r = 0; r < 4; r++) acc[ma][na][r] = 0.f;

        const uint32_t aBase = smem_u + OFF_A + b * A_BUF_SZ;
#pragma unroll
        for (int ks = 0; ks < 8; ks++) {
            const uint32_t ka = (uint32_t)ks * 32u;
            uint32_t ah0[4], ah1[4];
            ldsm_x4(ah0, aBase + a_off + ka);
            ldsm_x4(ah1, aBase + a_off + 16u * STRIDE_AB + ka);
#pragma unroll
            for (int np = 0; np < 4; np++) {
                uint32_t bq[4];
                ldsm_x4(bq, smem_u + OFF_BH + b4_off +
                            (uint32_t)np * 16u * STRIDE_AB + ka);
                mma_bf16(acc[0][2 * np],     ah0, &bq[0]);
                mma_bf16(acc[1][2 * np],     ah1, &bq[0]);
                mma_bf16(acc[0][2 * np + 1], ah0, &bq[2]);
                mma_bf16(acc[1][2 * np + 1], ah1, &bq[2]);
            }
        }

        const int tn = t + stride;
        if (tn < numTiles) produce(tn, b ^ 1);

#pragma unroll
        for (int ma = 0; ma < 2; ma++) {
#pragma unroll
            for (int hl = 0; hl < 2; hl++) {
                const int row = wm * 32 + ma * 16 + q + hl * 8;
                const float s = s_pol[b * TILE_E + row];
                const float* xr =
                    x + (size_t)s_src[b * TILE_E + row] * D_IN + wn * 64;
                float* hd =
                    g_h + (size_t)s_dst[b * TILE_E + row] * D_IN + wn * 64;
#pragma unroll
                for (int na = 0; na < 8; na++) {
                    const int cl = na * 8 + cp;
                    const int col = wn * 64 + cl;
                    float v0 = acc[ma][na][hl * 2 + 0];
                    float v1 = acc[ma][na][hl * 2 + 1];
                    float2 bb = *(const float2*)&s_b2l[col];
                    float2 ll = *(const float2*)&s_leb[col];
                    float2 xv = *(const float2*)(xr + cl);
                    float m0 = fmaxf(fmaf(s, v0 + bb.x, ll.x) + xv.x, 0.f);
                    float m1 = fmaxf(fmaf(s, v1 + bb.y, ll.y) + xv.y, 0.f);
                    red_v2(hd + cl, m0, m1);
                }
            }
        }

        bufp ^= 1;
        __syncthreads();
    }
}

// ---------------- node GEMM kernels (HMMA, 3-term bf16 emulation) ----------
#define NOFF_BH   0          // B hi chunk [256n][272B]
#define NOFF_BL   69632
#define NOFF_AH   139264     // A hi chunk [128m][272B]
#define NOFF_AL   174080
#define NOFF_PART 208896     // [128][4][2] f32 partial sums (node1 LN)
#define NOFF_B    212992     // bias 256 f
#define NOFF_LNG  214016
#define NOFF_LNB  215040
#define NODE_SMEM 216064
#define N_TILES_M ((N_NODES + 127) / 128)   // 391

template <bool WITH_LN>
__device__ __forceinline__ void node_gemm_body(
    const float* __restrict__ Asrc, const __nv_bfloat16* __restrict__ Wh,
    const __nv_bfloat16* __restrict__ Wl, const float* __restrict__ bias,
    const float* __restrict__ ln_g, const float* __restrict__ ln_b,
    float* __restrict__ Dst) {
    extern __shared__ char smem[];
    const uint32_t smem_u = smem_to_u32(smem);
    float* s_part = (float*)(smem + NOFF_PART);
    float* s_b    = (float*)(smem + NOFF_B);
    float* s_lng  = (float*)(smem + NOFF_LNG);
    float* s_lnb  = (float*)(smem + NOFF_LNB);

    const int tid = threadIdx.x;
    const int wid = tid >> 5;
    const int lane = tid & 31;
    const int r0 = blockIdx.x * 128;

    if (tid < D_IN) {
        s_b[tid] = bias[tid];
        if (WITH_LN) { s_lng[tid] = ln_g[tid]; s_lnb[tid] = ln_b[tid]; }
    }

    const int wm = wid & 3;
    const int wn = wid >> 2;
    const uint32_t a_off = (uint32_t)(wm * 32 + (lane & 15)) * STRIDE_AB +
                           (uint32_t)(lane >> 4) * 16u;
    const uint32_t b4_off = (uint32_t)(wn * 64 + ((lane >> 4) & 1) * 8 +
                                       (lane & 7)) * STRIDE_AB +
                            (uint32_t)((lane >> 3) & 1) * 16u;
    const int q  = lane >> 2;
    const int cp = (lane & 3) * 2;

    float acc[2][8][4];
#pragma unroll
    for (int ma = 0; ma < 2; ma++)
#pragma unroll
        for (int na = 0; na < 8; na++)
#pragma unroll
            for (int r = 0; r < 4; r++) acc[ma][na][r] = 0.f;

    for (int kc = 0; kc < 2; kc++) {
        for (int i = tid; i < 256 * 16; i += 512) {
            int n = i >> 4, c = i & 15;
            const size_t src = (size_t)n * D_IN + kc * 128 + c * 8;
            *(uint4*)(smem + NOFF_BH + (uint32_t)n * STRIDE_AB + c * 16) =
                *(const uint4*)(Wh + src);
            *(uint4*)(smem + NOFF_BL + (uint32_t)n * STRIDE_AB + c * 16) =
                *(const uint4*)(Wl + src);
        }
        for (int i = tid; i < 128 * 32; i += 512) {
            int r = i >> 5, c4 = i & 31;
            int rr = min(r0 + r, N_NODES - 1);
            float4 v = *(const float4*)&Asrc[(size_t)rr * D_IN + kc * 128 + c4 * 4];
            __nv_bfloat162 h01, h23, l01, l23;
            h01.x = __float2bfloat16(v.x); h01.y = __float2bfloat16(v.y);
            h23.x = __float2bfloat16(v.z); h23.y = __float2bfloat16(v.w);
            l01.x = __float2bfloat16(v.x - __bfloat162float(h01.x));
            l01.y = __float2bfloat16(v.y - __bfloat162float(h01.y));
            l23.x = __float2bfloat16(v.z - __bfloat162float(h23.x));
            l23.y = __float2bfloat16(v.w - __bfloat162float(h23.y));
            uint32_t off = (uint32_t)r * STRIDE_AB + c4 * 8;
            *(uint2*)(smem + NOFF_AH + off) =
                make_uint2(*(uint32_t*)&h01, *(uint32_t*)&h23);
            *(uint2*)(smem + NOFF_AL + off) =
                make_uint2(*(uint32_t*)&l01, *(uint32_t*)&l23);
        }
        __syncthreads();

#pragma unroll
        for (int ks = 0; ks < 8; ks++) {
            const uint32_t ka = (uint32_t)ks * 32u;
            uint32_t ah0[4], ah1[4], al0[4], al1[4];
            ldsm_x4(ah0, smem_u + NOFF_AH + a_off + ka);
            ldsm_x4(ah1, smem_u + NOFF_AH + a_off + 16u * STRIDE_AB + ka);
            ldsm_x4(al0, smem_u + NOFF_AL + a_off + ka);
            ldsm_x4(al1, smem_u + NOFF_AL + a_off + 16u * STRIDE_AB + ka);
#pragma unroll
            for (int np = 0; np < 4; np++) {
                uint32_t bh[4], bl[4];
                const uint32_t bo = b4_off + (uint32_t)np * 16u * STRIDE_AB + ka;
                ldsm_x4(bh, smem_u + NOFF_BH + bo);
                ldsm_x4(bl, smem_u + NOFF_BL + bo);
                mma_bf16(acc[0][2 * np],     ah0, &bh[0]);
                mma_bf16(acc[1][2 * np],     ah1, &bh[0]);
                mma_bf16(acc[0][2 * np],     al0, &bh[0]);
                mma_bf16(acc[1][2 * np],     al1, &bh[0]);
                mma_bf16(acc[0][2 * np],     ah0, &bl[0]);
                mma_bf16(acc[1][2 * np],     ah1, &bl[0]);
                mma_bf16(acc[0][2 * np + 1], ah0, &bh[2]);
                mma_bf16(acc[1][2 * np + 1], ah1, &bh[2]);
                mma_bf16(acc[0][2 * np + 1], al0, &bh[2]);
                mma_bf16(acc[1][2 * np + 1], al1, &bh[2]);
                mma_bf16(acc[0][2 * np + 1], ah0, &bl[2]);
                mma_bf16(acc[1][2 * np + 1], ah1, &bl[2]);
            }
        }
        __syncthreads();
    }

    float bcol[8][2];
#pragma unroll
    for (int na = 0; na < 8; na++) {
        bcol[na][0] = s_b[wn * 64 + na * 8 + cp];
        bcol[na][1] = s_b[wn * 64 + na * 8 + cp + 1];
    }
#pragma unroll
    for (int ma = 0; ma < 2; ma++)
#pragma unroll
        for (int na = 0; na < 8; na++)
#pragma unroll
            for (int hl = 0; hl < 2; hl++) {
                acc[ma][na][hl * 2 + 0] += bcol[na][0];
                acc[ma][na][hl * 2 + 1] += bcol[na][1];
            }

    if (WITH_LN) {
#pragma unroll
        for (int ma = 0; ma < 2; ma++)
#pragma unroll
            for (int hl = 0; hl < 2; hl++) {
                float s = 0.f, ss = 0.f;
#pragma unroll
                for (int na = 0; na < 8; na++) {
                    float v0 = acc[ma][na][hl * 2 + 0];
                    float v1 = acc[ma][na][hl * 2 + 1];
                    s += v0 + v1;
                    ss = fmaf(v0, v0, ss); ss = fmaf(v1, v1, ss);
                }
                s  += __shfl_xor_sync(0xffffffffu, s, 1);
                s  += __shfl_xor_sync(0xffffffffu, s, 2);
                ss += __shfl_xor_sync(0xffffffffu, ss, 1);
                ss += __shfl_xor_sync(0xffffffffu, ss, 2);
                if ((lane & 3) == 0) {
                    const int row = wm * 32 + ma * 16 + hl * 8 + q;
                    *(float2*)&s_part[row * 8 + wn * 2] = make_float2(s, ss);
                }
            }
        __syncthreads();

#pragma unroll
        for (int ma = 0; ma < 2; ma++)
#pragma unroll
            for (int hl = 0; hl < 2; hl++) {
                const int row = wm * 32 + ma * 16 + hl * 8 + q;
                float sum = 0.f, ssum = 0.f;
#pragma unroll
                for (int w = 0; w < 4; w++) {
                    float2 p = *(const float2*)&s_part[row * 8 + w * 2];
                    sum += p.x; ssum += p.y;
                }
                const float mu = sum * (1.f / D_IN);
                const float var =
                    fmaxf(ssum * (1.f / D_IN) - mu * mu, 0.f);
                const float rstd = rsqrtf(var + LN_EPS);
                const int grow = r0 + row;
                if (grow < N_NODES) {
#pragma unroll
                    for (int na = 0; na < 8; na++) {
                        const int col = wn * 64 + na * 8 + cp;
                        float g0 = s_lng[col], g1 = s_lng[col + 1];
                        float l0 = s_lnb[col], l1 = s_lnb[col + 1];
                        float o0 = fmaxf(
                            fmaf((acc[ma][na][hl * 2] - mu) * rstd, g0, l0), 0.f);
                        float o1 = fmaxf(
                            fmaf((acc[ma][na][hl * 2 + 1] - mu) * rstd, g1, l1),
                            0.f);
                        *(float2*)&Dst[(size_t)grow * D_IN + col] =
                            make_float2(o0, o1);
                    }
                }
            }
    } else {
#pragma unroll
        for (int ma = 0; ma < 2; ma++)
#pragma unroll
            for (int hl = 0; hl < 2; hl++) {
                const int row = wm * 32 + ma * 16 + hl * 8 + q;
                const int grow = r0 + row;
                if (grow < N_NODES) {
#pragma unroll
                    for (int na = 0; na < 8; na++) {
                        const int col = wn * 64 + na * 8 + cp;
                        *(float2*)&Dst[(size_t)grow * D_IN + col] =
                            make_float2(acc[ma][na][hl * 2],
                                        acc[ma][na][hl * 2 + 1]);
                    }
                }
            }
    }
}

__global__ __launch_bounds__(512, 1)
void node1_kernel(const float* __restrict__ b1, const float* __restrict__ ln_g,
                  const float* __restrict__ ln_b) {
    node_gemm_body<true>(g_h, g_W1h, g_W1l, b1, ln_g, ln_b, g_t);
}

__global__ __launch_bounds__(512, 1)
void node2_kernel(const float* __restrict__ b2, float* __restrict__ out) {
    node_gemm_body<false>(g_t, g_W2h, g_W2l, b2, nullptr, nullptr, out);
}

// ---------------- launcher --------------------------------------------------
extern "C" void kernel_launch(void* const* d_in, const int* in_sizes, int n_in,
                              void* d_out, int out_size) {
    const float* x    = (const float*)d_in[0];
    const void*  ei   = d_in[1];
    const float* ea   = (const float*)d_in[2];
    const float* ew1  = (const float*)d_in[3];
    const float* eb1  = (const float*)d_in[4];
    const float* ew2  = (const float*)d_in[5];
    const float* eb2  = (const float*)d_in[6];
    const float* lew  = (const float*)d_in[7];
    const float* leb  = (const float*)d_in[8];
    const float* w1   = (const float*)d_in[9];
    const float* b1   = (const float*)d_in[10];
    const float* ln_g = (const float*)d_in[11];
    const float* ln_b = (const float*)d_in[12];
    const float* w2   = (const float*)d_in[13];
    const float* b2   = (const float*)d_in[14];
    float* out = (float*)d_out;

    cudaFuncSetAttribute(edge_kernel, cudaFuncAttributeMaxDynamicSharedMemorySize,
                         EDGE_SMEM);
    cudaFuncSetAttribute(node1_kernel, cudaFuncAttributeMaxDynamicSharedMemorySize,
                         NODE_SMEM);
    cudaFuncSetAttribute(node2_kernel, cudaFuncAttributeMaxDynamicSharedMemorySize,
                         NODE_SMEM);

    detect_idx_kernel<<<1, 32>>>((const int*)ei);
    precompute_kernel<<<128, 256>>>(ew2, lew, eb2);
    split_w_kernel<<<256, 256>>>(w1, 0);
    split_w_kernel<<<256, 256>>>(w2, 1);
    init_h_kernel<<<1184, 256>>>(x);
    edge_kernel<<<148, 512, EDGE_SMEM>>>(x, ei, ea, ew1, eb1, leb);
    node1_kernel<<<N_TILES_M, 512, NODE_SMEM>>>(b1, ln_g, ln_b);
    node2_kernel<<<N_TILES_M, 512, NODE_SMEM>>>(b2, out);
}

// round 10
// speedup vs baseline: 2.9450x; 1.1091x over previous
#include <cuda_runtime.h>
#include <cuda_bf16.h>
#include <cstdint>

#define N_NODES 50000
#define N_EDGES 800000
#define D_IN    256
#define D_HID   128
#define D_RAW   16
#define TILE_E  128
#define LN_EPS  1e-5f

static_assert(N_EDGES % TILE_E == 0, "edge tiling assumes exact division");

// ---------------- portable warp-MMA helpers (sm_80+ PTX) -------------------
__device__ __forceinline__ uint32_t smem_to_u32(const void* p) {
    uint32_t a;
    asm("{ .reg .u64 t; cvta.to.shared.u64 t, %1; cvt.u32.u64 %0, t; }"
        : "=r"(a) : "l"(p));
    return a;
}
__device__ __forceinline__ void ldsm_x4(uint32_t* r, uint32_t addr) {
    asm volatile("ldmatrix.sync.aligned.m8n8.x4.shared.b16 {%0,%1,%2,%3}, [%4];"
                 : "=r"(r[0]), "=r"(r[1]), "=r"(r[2]), "=r"(r[3]) : "r"(addr));
}
__device__ __forceinline__ void mma_bf16(float* d, const uint32_t* a,
                                         const uint32_t* b) {
    asm volatile(
        "mma.sync.aligned.m16n8k16.row.col.f32.bf16.bf16.f32 "
        "{%0,%1,%2,%3}, {%4,%5,%6,%7}, {%8,%9}, {%0,%1,%2,%3};"
        : "+f"(d[0]), "+f"(d[1]), "+f"(d[2]), "+f"(d[3])
        : "r"(a[0]), "r"(a[1]), "r"(a[2]), "r"(a[3]), "r"(b[0]), "r"(b[1]));
}
__device__ __forceinline__ void red_v4(float* gptr, float a, float b,
                                       float c, float d) {
    asm volatile("red.global.add.v4.f32 [%0], {%1, %2, %3, %4};"
                 :: "l"(gptr), "f"(a), "f"(b), "f"(c), "f"(d) : "memory");
}

// ---------------- scratch (device globals; no runtime allocation) ----------
__device__ float g_b2l[D_IN];                                 // eb2 @ lew
__device__ __align__(16) __nv_bfloat16 g_Bh[D_IN * D_HID];    // bf16(W2L^T) [n][k]
__device__ __align__(16) __nv_bfloat16 g_W1h[D_IN * D_IN];    // w1^T hi [n][k]
__device__ __align__(16) __nv_bfloat16 g_W1l[D_IN * D_IN];    // w1^T lo
__device__ __align__(16) __nv_bfloat16 g_W2h[D_IN * D_IN];    // w2^T hi
__device__ __align__(16) __nv_bfloat16 g_W2l[D_IN * D_IN];    // w2^T lo
__device__ float g_h[(size_t)N_NODES * D_IN];                 // x + aggr
__device__ float g_t[(size_t)N_NODES * D_IN];                 // relu(LN(h@w1+b1))
__device__ int   g_is64;                                      // dtype flag

// ---------------- K-1: detect edge_index dtype ------------------------------
__global__ void detect_idx_kernel(const int* __restrict__ ei32) {
    if (threadIdx.x == 0 && blockIdx.x == 0) {
        int is64 = 1;
        for (int i = 0; i < 64; i++)
            if (ei32[2 * i + 1] != 0) { is64 = 0; break; }
        g_is64 = is64;
    }
}

// ---------------- K0a: fold ew2 @ lew, bf16 hi part -------------------------
__global__ void precompute_kernel(const float* __restrict__ ew2,
                                  const float* __restrict__ lew,
                                  const float* __restrict__ eb2) {
    int idx = blockIdx.x * blockDim.x + threadIdx.x;   // 0..32767
    int k = idx >> 8;      // 0..127 (hid)
    int n = idx & 255;     // 0..255 (out col)
    float s = 0.f;
#pragma unroll 8
    for (int j = 0; j < D_HID; j++)
        s = fmaf(ew2[k * D_HID + j], lew[j * D_IN + n], s);
    g_Bh[n * D_HID + k] = __float2bfloat16(s);
    if (idx < D_IN) {
        float b = 0.f;
        for (int j = 0; j < D_HID; j++)
            b = fmaf(eb2[j], lew[j * D_IN + idx], b);
        g_b2l[idx] = b;
    }
}

// ---------------- K0b: transpose + split node weights -----------------------
__global__ void split_w_kernel(const float* __restrict__ w, int which) {
    __nv_bfloat16* Wh = which ? g_W2h : g_W1h;
    __nv_bfloat16* Wl = which ? g_W2l : g_W1l;
    int idx = blockIdx.x * blockDim.x + threadIdx.x;   // 0..65535
    int k = idx >> 8, n = idx & 255;
    float v = w[k * D_IN + n];
    __nv_bfloat16 hi = __float2bfloat16(v);
    Wh[n * D_IN + k] = hi;
    Wl[n * D_IN + k] = __float2bfloat16(v - __bfloat162float(hi));
}

// ---------------- K1: g_h = x ----------------------------------------------
__global__ void init_h_kernel(const float* __restrict__ x) {
    const size_t total = (size_t)N_NODES * D_IN / 4;
    const float4* xs = (const float4*)x;
    float4* hs = (float4*)g_h;
    for (size_t i = (size_t)blockIdx.x * blockDim.x + threadIdx.x; i < total;
         i += (size_t)gridDim.x * blockDim.x)
        hs[i] = xs[i];
}

// ---------------- K2: pipelined edge kernel (1-term bf16: Ah @ Bh^T) --------
// B rows stored PERMUTED so each lane's fragment pair (na=2p, 2p+1) covers 4
// contiguous global columns -> LDG.128 gather + red.v4 scatter.
// fragment pos j(na,c) holds global col G = 16*(na>>1) + 4*(c>>1) + 2*(na&1) + (c&1)
#define STRIDE_AB 272
#define OFF_BH   0          // 256*272 = 69632
#define OFF_A    69632      // 2 bufs x 128*272 = 69632 (hi split only)
#define A_BUF_SZ 34816
#define OFF_EW1  139264     // 8192
#define OFF_RAW  147456     // 8192
#define OFF_EB1  155648     // 512
#define OFF_B2L  156160     // 1024
#define OFF_LEB  157184     // 1024
#define OFF_POL  158208     // 2 x 512
#define OFF_SRC  159232     // 2 x 512
#define OFF_DST  160256     // 2 x 512
#define EDGE_SMEM 161280

__global__ __launch_bounds__(512, 1)
void edge_kernel(const float* __restrict__ x,
                 const void* __restrict__ ei_raw,
                 const float* __restrict__ ea,
                 const float* __restrict__ ew1,
                 const float* __restrict__ eb1,
                 const float* __restrict__ leb) {
    extern __shared__ char smem[];
    const uint32_t smem_u = smem_to_u32(smem);
    float* s_ew1 = (float*)(smem + OFF_EW1);
    float* s_raw = (float*)(smem + OFF_RAW);
    float* s_eb1 = (float*)(smem + OFF_EB1);
    float* s_b2l = (float*)(smem + OFF_B2L);
    float* s_leb = (float*)(smem + OFF_LEB);
    float* s_pol = (float*)(smem + OFF_POL);
    int*   s_src = (int*)(smem + OFF_SRC);
    int*   s_dst = (int*)(smem + OFF_DST);

    const int tid = threadIdx.x;
    const int wid = tid >> 5;
    const int lane = tid & 31;
    const int is64 = g_is64;
    const long long* ei64 = (const long long*)ei_raw;
    const int*       ei32 = (const int*)ei_raw;

    // B staging with N-permutation: global col G -> fragment row position
    for (int w = tid; w < 256 * 64; w += 512) {
        int G = w >> 6, k2 = w & 63;
        int wnb = G >> 6;            // 64-col block (matches warp wn)
        int gl = G & 63;             // col within block
        int na = 2 * (gl >> 4) + ((gl >> 1) & 1);
        int c  = 2 * ((gl >> 2) & 3) + (gl & 1);
        int n  = wnb * 64 + na * 8 + c;   // fragment row
        *(uint32_t*)(smem + OFF_BH + (uint32_t)n * STRIDE_AB + (uint32_t)k2 * 4u)
            = ((const uint32_t*)g_Bh)[w];
    }
    for (int i = tid; i < D_RAW * D_HID; i += 512) s_ew1[i] = ew1[i];
    if (tid < D_HID) s_eb1[tid] = eb1[tid];
    if (tid < D_IN) { s_b2l[tid] = g_b2l[tid]; s_leb[tid] = leb[tid]; }
    __syncthreads();

    const int numTiles = N_EDGES / TILE_E;
    const int stride = gridDim.x;

    // warp-local producer: load 8 edges + stage1 -> A[buf] (hi split only)
    auto produce = [&](int t, int bb) {
        const int e0 = t * TILE_E;
        const int er0 = wid * 8;
        for (int i = lane; i < 8 * 17; i += 32) {
            int le = i / 17, c = i % 17;
            float v = ea[(size_t)(e0 + er0 + le) * 17 + c];
            if (c == 0)
                s_pol[bb * TILE_E + er0 + le] = fminf(fmaxf(v, 0.f), 1.f) + 0.01f;
            else
                s_raw[(er0 + le) * D_RAW + (c - 1)] = v;
        }
        if (lane < 8) {
            int sv = is64 ? (int)ei64[e0 + er0 + lane] : ei32[e0 + er0 + lane];
            s_src[bb * TILE_E + er0 + lane] = min(max(sv, 0), N_NODES - 1);
        } else if (lane < 16) {
            int l8 = lane - 8;
            int dv = is64 ? (int)ei64[N_EDGES + e0 + er0 + l8]
                          : ei32[N_EDGES + e0 + er0 + l8];
            s_dst[bb * TILE_E + er0 + l8] = min(max(dv, 0), N_NODES - 1);
        }
        __syncwarp();

        const int c0 = lane * 4;
        float4 a4[8];
        float4 eb4 = *(const float4*)&s_eb1[c0];
#pragma unroll
        for (int e = 0; e < 8; e++) a4[e] = eb4;
#pragma unroll
        for (int kb = 0; kb < 4; kb++) {
            float4 w0 = *(const float4*)&s_ew1[(kb * 4 + 0) * D_HID + c0];
            float4 w1 = *(const float4*)&s_ew1[(kb * 4 + 1) * D_HID + c0];
            float4 w2 = *(const float4*)&s_ew1[(kb * 4 + 2) * D_HID + c0];
            float4 w3 = *(const float4*)&s_ew1[(kb * 4 + 3) * D_HID + c0];
#pragma unroll
            for (int e = 0; e < 8; e++) {
                float4 r = *(const float4*)&s_raw[(er0 + e) * D_RAW + kb * 4];
                float4 a = a4[e];
                a.x = fmaf(r.x, w0.x, a.x); a.y = fmaf(r.x, w0.y, a.y);
                a.z = fmaf(r.x, w0.z, a.z); a.w = fmaf(r.x, w0.w, a.w);
                a.x = fmaf(r.y, w1.x, a.x); a.y = fmaf(r.y, w1.y, a.y);
                a.z = fmaf(r.y, w1.z, a.z); a.w = fmaf(r.y, w1.w, a.w);
                a.x = fmaf(r.z, w2.x, a.x); a.y = fmaf(r.z, w2.y, a.y);
                a.z = fmaf(r.z, w2.z, a.z); a.w = fmaf(r.z, w2.w, a.w);
                a.x = fmaf(r.w, w3.x, a.x); a.y = fmaf(r.w, w3.y, a.y);
                a.z = fmaf(r.w, w3.z, a.z); a.w = fmaf(r.w, w3.w, a.w);
                a4[e] = a;
            }
        }
        char* ah = smem + OFF_A + bb * A_BUF_SZ + (er0 * STRIDE_AB) + lane * 8;
#pragma unroll
        for (int e = 0; e < 8; e++) {
            float4 a = a4[e];
            __nv_bfloat162 h01, h23;
            h01.x = __float2bfloat16(fmaxf(a.x, 0.f));
            h01.y = __float2bfloat16(fmaxf(a.y, 0.f));
            h23.x = __float2bfloat16(fmaxf(a.z, 0.f));
            h23.y = __float2bfloat16(fmaxf(a.w, 0.f));
            *(uint2*)(ah + e * STRIDE_AB) =
                make_uint2(*(uint32_t*)&h01, *(uint32_t*)&h23);
        }
    };

    const int wm = wid & 3;
    const int wn = wid >> 2;
    const uint32_t a_off = (uint32_t)(wm * 32 + (lane & 15)) * STRIDE_AB +
                           (uint32_t)(lane >> 4) * 16u;
    const uint32_t b4_off = (uint32_t)(wn * 64 + ((lane >> 4) & 1) * 8 +
                                       (lane & 7)) * STRIDE_AB +
                            (uint32_t)((lane >> 3) & 1) * 16u;
    const int q  = lane >> 2;

    produce(blockIdx.x, 0);
    __syncthreads();

    int bufp = 0;
    for (int t = blockIdx.x; t < numTiles; t += stride) {
        const int b = bufp;

        float acc[2][8][4];
#pragma unroll
        for (int ma = 0; ma < 2; ma++)
#pragma unroll
            for (int na = 0; na < 8; na++)
#pragma unroll
                for (int r = 0; r < 4; r++) acc[ma][na][r] = 0.f;

        const uint32_t aBase = smem_u + OFF_A + b * A_BUF_SZ;
#pragma unroll
        for (int ks = 0; ks < 8; ks++) {
            const uint32_t ka = (uint32_t)ks * 32u;
            uint32_t ah0[4], ah1[4];
            ldsm_x4(ah0, aBase + a_off + ka);
            ldsm_x4(ah1, aBase + a_off + 16u * STRIDE_AB + ka);
#pragma unroll
            for (int np = 0; np < 4; np++) {
                uint32_t bq[4];
                ldsm_x4(bq, smem_u + OFF_BH + b4_off +
                            (uint32_t)np * 16u * STRIDE_AB + ka);
                mma_bf16(acc[0][2 * np],     ah0, &bq[0]);
                mma_bf16(acc[1][2 * np],     ah1, &bq[0]);
                mma_bf16(acc[0][2 * np + 1], ah0, &bq[2]);
                mma_bf16(acc[1][2 * np + 1], ah1, &bq[2]);
            }
        }

        const int tn = t + stride;
        if (tn < numTiles) produce(tn, b ^ 1);

        // ---- epilogue: 4-wide gather + relu + red.v4 (permuted cols) ----
#pragma unroll
        for (int ma = 0; ma < 2; ma++) {
#pragma unroll
            for (int hl = 0; hl < 2; hl++) {
                const int row = wm * 32 + ma * 16 + q + hl * 8;
                const float s = s_pol[b * TILE_E + row];
                const float* xr =
                    x + (size_t)s_src[b * TILE_E + row] * D_IN + wn * 64;
                float* hd =
                    g_h + (size_t)s_dst[b * TILE_E + row] * D_IN + wn * 64;
#pragma unroll
                for (int p = 0; p < 4; p++) {
                    const int cl = p * 16 + (lane & 3) * 4;  // local col (4-aligned)
                    const int col = wn * 64 + cl;
                    float4 bb = *(const float4*)&s_b2l[col];
                    float4 ll = *(const float4*)&s_leb[col];
                    float4 xv = *(const float4*)(xr + cl);
                    float m0 = fmaxf(
                        fmaf(s, acc[ma][2 * p][hl * 2 + 0] + bb.x, ll.x) + xv.x,
                        0.f);
                    float m1 = fmaxf(
                        fmaf(s, acc[ma][2 * p][hl * 2 + 1] + bb.y, ll.y) + xv.y,
                        0.f);
                    float m2 = fmaxf(
                        fmaf(s, acc[ma][2 * p + 1][hl * 2 + 0] + bb.z, ll.z) +
                            xv.z, 0.f);
                    float m3 = fmaxf(
                        fmaf(s, acc[ma][2 * p + 1][hl * 2 + 1] + bb.w, ll.w) +
                            xv.w, 0.f);
                    red_v4(hd + cl, m0, m1, m2, m3);
                }
            }
        }

        bufp ^= 1;
        __syncthreads();
    }
}

// ---------------- node GEMM kernels (HMMA, 3-term bf16 emulation) ----------
#define NOFF_BH   0          // B hi chunk [256n][272B]
#define NOFF_BL   69632
#define NOFF_AH   139264     // A hi chunk [128m][272B]
#define NOFF_AL   174080
#define NOFF_PART 208896     // [128][4][2] f32 partial sums (node1 LN)
#define NOFF_B    212992     // bias 256 f
#define NOFF_LNG  214016
#define NOFF_LNB  215040
#define NODE_SMEM 216064
#define N_TILES_M ((N_NODES + 127) / 128)   // 391

template <bool WITH_LN>
__device__ __forceinline__ void node_gemm_body(
    const float* __restrict__ Asrc, const __nv_bfloat16* __restrict__ Wh,
    const __nv_bfloat16* __restrict__ Wl, const float* __restrict__ bias,
    const float* __restrict__ ln_g, const float* __restrict__ ln_b,
    float* __restrict__ Dst) {
    extern __shared__ char smem[];
    const uint32_t smem_u = smem_to_u32(smem);
    float* s_part = (float*)(smem + NOFF_PART);
    float* s_b    = (float*)(smem + NOFF_B);
    float* s_lng  = (float*)(smem + NOFF_LNG);
    float* s_lnb  = (float*)(smem + NOFF_LNB);

    const int tid = threadIdx.x;
    const int wid = tid >> 5;
    const int lane = tid & 31;
    const int r0 = blockIdx.x * 128;

    if (tid < D_IN) {
        s_b[tid] = bias[tid];
        if (WITH_LN) { s_lng[tid] = ln_g[tid]; s_lnb[tid] = ln_b[tid]; }
    }

    const int wm = wid & 3;
    const int wn = wid >> 2;
    const uint32_t a_off = (uint32_t)(wm * 32 + (lane & 15)) * STRIDE_AB +
                           (uint32_t)(lane >> 4) * 16u;
    const uint32_t b4_off = (uint32_t)(wn * 64 + ((lane >> 4) & 1) * 8 +
                                       (lane & 7)) * STRIDE_AB +
                            (uint32_t)((lane >> 3) & 1) * 16u;
    const int q  = lane >> 2;
    const int cp = (lane & 3) * 2;

    float acc[2][8][4];
#pragma unroll
    for (int ma = 0; ma < 2; ma++)
#pragma unroll
        for (int na = 0; na < 8; na++)
#pragma unroll
            for (int r = 0; r < 4; r++) acc[ma][na][r] = 0.f;

    for (int kc = 0; kc < 2; kc++) {
        for (int i = tid; i < 256 * 16; i += 512) {
            int n = i >> 4, c = i & 15;
            const size_t src = (size_t)n * D_IN + kc * 128 + c * 8;
            *(uint4*)(smem + NOFF_BH + (uint32_t)n * STRIDE_AB + c * 16) =
                *(const uint4*)(Wh + src);
            *(uint4*)(smem + NOFF_BL + (uint32_t)n * STRIDE_AB + c * 16) =
                *(const uint4*)(Wl + src);
        }
        for (int i = tid; i < 128 * 32; i += 512) {
            int r = i >> 5, c4 = i & 31;
            int rr = min(r0 + r, N_NODES - 1);
            float4 v = *(const float4*)&Asrc[(size_t)rr * D_IN + kc * 128 + c4 * 4];
            __nv_bfloat162 h01, h23, l01, l23;
            h01.x = __float2bfloat16(v.x); h01.y = __float2bfloat16(v.y);
            h23.x = __float2bfloat16(v.z); h23.y = __float2bfloat16(v.w);
            l01.x = __float2bfloat16(v.x - __bfloat162float(h01.x));
            l01.y = __float2bfloat16(v.y - __bfloat162float(h01.y));
            l23.x = __float2bfloat16(v.z - __bfloat162float(h23.x));
            l23.y = __float2bfloat16(v.w - __bfloat162float(h23.y));
            uint32_t off = (uint32_t)r * STRIDE_AB + c4 * 8;
            *(uint2*)(smem + NOFF_AH + off) =
                make_uint2(*(uint32_t*)&h01, *(uint32_t*)&h23);
            *(uint2*)(smem + NOFF_AL + off) =
                make_uint2(*(uint32_t*)&l01, *(uint32_t*)&l23);
        }
        __syncthreads();

#pragma unroll
        for (int ks = 0; ks < 8; ks++) {
            const uint32_t ka = (uint32_t)ks * 32u;
            uint32_t ah0[4], ah1[4], al0[4], al1[4];
            ldsm_x4(ah0, smem_u + NOFF_AH + a_off + ka);
            ldsm_x4(ah1, smem_u + NOFF_AH + a_off + 16u * STRIDE_AB + ka);
            ldsm_x4(al0, smem_u + NOFF_AL + a_off + ka);
            ldsm_x4(al1, smem_u + NOFF_AL + a_off + 16u * STRIDE_AB + ka);
#pragma unroll
            for (int np = 0; np < 4; np++) {
                uint32_t bh[4], bl[4];
                const uint32_t bo = b4_off + (uint32_t)np * 16u * STRIDE_AB + ka;
                ldsm_x4(bh, smem_u + NOFF_BH + bo);
                ldsm_x4(bl, smem_u + NOFF_BL + bo);
                mma_bf16(acc[0][2 * np],     ah0, &bh[0]);
                mma_bf16(acc[1][2 * np],     ah1, &bh[0]);
                mma_bf16(acc[0][2 * np],     al0, &bh[0]);
                mma_bf16(acc[1][2 * np],     al1, &bh[0]);
                mma_bf16(acc[0][2 * np],     ah0, &bl[0]);
                mma_bf16(acc[1][2 * np],     ah1, &bl[0]);
                mma_bf16(acc[0][2 * np + 1], ah0, &bh[2]);
                mma_bf16(acc[1][2 * np + 1], ah1, &bh[2]);
                mma_bf16(acc[0][2 * np + 1], al0, &bh[2]);
                mma_bf16(acc[1][2 * np + 1], al1, &bh[2]);
                mma_bf16(acc[0][2 * np + 1], ah0, &bl[2]);
                mma_bf16(acc[1][2 * np + 1], ah1, &bl[2]);
            }
        }
        __syncthreads();
    }

    float bcol[8][2];
#pragma unroll
    for (int na = 0; na < 8; na++) {
        bcol[na][0] = s_b[wn * 64 + na * 8 + cp];
        bcol[na][1] = s_b[wn * 64 + na * 8 + cp + 1];
    }
#pragma unroll
    for (int ma = 0; ma < 2; ma++)
#pragma unroll
        for (int na = 0; na < 8; na++)
#pragma unroll
            for (int hl = 0; hl < 2; hl++) {
                acc[ma][na][hl * 2 + 0] += bcol[na][0];
                acc[ma][na][hl * 2 + 1] += bcol[na][1];
            }

    if (WITH_LN) {
#pragma unroll
        for (int ma = 0; ma < 2; ma++)
#pragma unroll
            for (int hl = 0; hl < 2; hl++) {
                float s = 0.f, ss = 0.f;
#pragma unroll
                for (int na = 0; na < 8; na++) {
                    float v0 = acc[ma][na][hl * 2 + 0];
                    float v1 = acc[ma][na][hl * 2 + 1];
                    s += v0 + v1;
                    ss = fmaf(v0, v0, ss); ss = fmaf(v1, v1, ss);
                }
                s  += __shfl_xor_sync(0xffffffffu, s, 1);
                s  += __shfl_xor_sync(0xffffffffu, s, 2);
                ss += __shfl_xor_sync(0xffffffffu, ss, 1);
                ss += __shfl_xor_sync(0xffffffffu, ss, 2);
                if ((lane & 3) == 0) {
                    const int row = wm * 32 + ma * 16 + hl * 8 + q;
                    *(float2*)&s_part[row * 8 + wn * 2] = make_float2(s, ss);
                }
            }
        __syncthreads();

#pragma unroll
        for (int ma = 0; ma < 2; ma++)
#pragma unroll
            for (int hl = 0; hl < 2; hl++) {
                const int row = wm * 32 + ma * 16 + hl * 8 + q;
                float sum = 0.f, ssum = 0.f;
#pragma unroll
                for (int w = 0; w < 4; w++) {
                    float2 p = *(const float2*)&s_part[row * 8 + w * 2];
                    sum += p.x; ssum += p.y;
                }
                const float mu = sum * (1.f / D_IN);
                const float var =
                    fmaxf(ssum * (1.f / D_IN) - mu * mu, 0.f);
                const float rstd = rsqrtf(var + LN_EPS);
                const int grow = r0 + row;
                if (grow < N_NODES) {
#pragma unroll
                    for (int na = 0; na < 8; na++) {
                        const int col = wn * 64 + na * 8 + cp;
                        float g0 = s_lng[col], g1 = s_lng[col + 1];
                        float l0 = s_lnb[col], l1 = s_lnb[col + 1];
                        float o0 = fmaxf(
                            fmaf((acc[ma][na][hl * 2] - mu) * rstd, g0, l0), 0.f);
                        float o1 = fmaxf(
                            fmaf((acc[ma][na][hl * 2 + 1] - mu) * rstd, g1, l1),
                            0.f);
                        *(float2*)&Dst[(size_t)grow * D_IN + col] =
                            make_float2(o0, o1);
                    }
                }
            }
    } else {
#pragma unroll
        for (int ma = 0; ma < 2; ma++)
#pragma unroll
            for (int hl = 0; hl < 2; hl++) {
                const int row = wm * 32 + ma * 16 + hl * 8 + q;
                const int grow = r0 + row;
                if (grow < N_NODES) {
#pragma unroll
                    for (int na = 0; na < 8; na++) {
                        const int col = wn * 64 + na * 8 + cp;
                        *(float2*)&Dst[(size_t)grow * D_IN + col] =
                            make_float2(acc[ma][na][hl * 2],
                                        acc[ma][na][hl * 2 + 1]);
                    }
                }
            }
    }
}

__global__ __launch_bounds__(512, 1)
void node1_kernel(const float* __restrict__ b1, const float* __restrict__ ln_g,
                  const float* __restrict__ ln_b) {
    node_gemm_body<true>(g_h, g_W1h, g_W1l, b1, ln_g, ln_b, g_t);
}

__global__ __launch_bounds__(512, 1)
void node2_kernel(const float* __restrict__ b2, float* __restrict__ out) {
    node_gemm_body<false>(g_t, g_W2h, g_W2l, b2, nullptr, nullptr, out);
}

// ---------------- launcher --------------------------------------------------
extern "C" void kernel_launch(void* const* d_in, const int* in_sizes, int n_in,
                              void* d_out, int out_size) {
    const float* x    = (const float*)d_in[0];
    const void*  ei   = d_in[1];
    const float* ea   = (const float*)d_in[2];
    const float* ew1  = (const float*)d_in[3];
    const float* eb1  = (const float*)d_in[4];
    const float* ew2  = (const float*)d_in[5];
    const float* eb2  = (const float*)d_in[6];
    const float* lew  = (const float*)d_in[7];
    const float* leb  = (const float*)d_in[8];
    const float* w1   = (const float*)d_in[9];
    const float* b1   = (const float*)d_in[10];
    const float* ln_g = (const float*)d_in[11];
    const float* ln_b = (const float*)d_in[12];
    const float* w2   = (const float*)d_in[13];
    const float* b2   = (const float*)d_in[14];
    float* out = (float*)d_out;

    cudaFuncSetAttribute(edge_kernel, cudaFuncAttributeMaxDynamicSharedMemorySize,
                         EDGE_SMEM);
    cudaFuncSetAttribute(node1_kernel, cudaFuncAttributeMaxDynamicSharedMemorySize,
                         NODE_SMEM);
    cudaFuncSetAttribute(node2_kernel, cudaFuncAttributeMaxDynamicSharedMemorySize,
                         NODE_SMEM);

    detect_idx_kernel<<<1, 32>>>((const int*)ei);
    precompute_kernel<<<128, 256>>>(ew2, lew, eb2);
    split_w_kernel<<<256, 256>>>(w1, 0);
    split_w_kernel<<<256, 256>>>(w2, 1);
    init_h_kernel<<<1184, 256>>>(x);
    edge_kernel<<<148, 512, EDGE_SMEM>>>(x, ei, ea, ew1, eb1, leb);
    node1_kernel<<<N_TILES_M, 512, NODE_SMEM>>>(b1, ln_g, ln_b);
    node2_kernel<<<N_TILES_M, 512, NODE_SMEM>>>(b2, out);
}

// round 11
// speedup vs baseline: 3.1076x; 1.0552x over previous
#include <cuda_runtime.h>
#include <cuda_bf16.h>
#include <cstdint>

#define N_NODES 50000
#define N_EDGES 800000
#define D_IN    256
#define D_HID   128
#define D_RAW   16
#define TILE_E  64
#define LN_EPS  1e-5f

static_assert(N_EDGES % TILE_E == 0, "edge tiling assumes exact division");

// ---------------- portable warp-MMA helpers (sm_80+ PTX) -------------------
__device__ __forceinline__ uint32_t smem_to_u32(const void* p) {
    uint32_t a;
    asm("{ .reg .u64 t; cvta.to.shared.u64 t, %1; cvt.u32.u64 %0, t; }"
        : "=r"(a) : "l"(p));
    return a;
}
__device__ __forceinline__ void ldsm_x4(uint32_t* r, uint32_t addr) {
    asm volatile("ldmatrix.sync.aligned.m8n8.x4.shared.b16 {%0,%1,%2,%3}, [%4];"
                 : "=r"(r[0]), "=r"(r[1]), "=r"(r[2]), "=r"(r[3]) : "r"(addr));
}
__device__ __forceinline__ void mma_bf16(float* d, const uint32_t* a,
                                         const uint32_t* b) {
    asm volatile(
        "mma.sync.aligned.m16n8k16.row.col.f32.bf16.bf16.f32 "
        "{%0,%1,%2,%3}, {%4,%5,%6,%7}, {%8,%9}, {%0,%1,%2,%3};"
        : "+f"(d[0]), "+f"(d[1]), "+f"(d[2]), "+f"(d[3])
        : "r"(a[0]), "r"(a[1]), "r"(a[2]), "r"(a[3]), "r"(b[0]), "r"(b[1]));
}
__device__ __forceinline__ void red_v4(float* gptr, float a, float b,
                                       float c, float d) {
    asm volatile("red.global.add.v4.f32 [%0], {%1, %2, %3, %4};"
                 :: "l"(gptr), "f"(a), "f"(b), "f"(c), "f"(d) : "memory");
}

// ---------------- scratch (device globals; no runtime allocation) ----------
__device__ float g_b2l[D_IN];                                 // eb2 @ lew
__device__ __align__(16) __nv_bfloat16 g_Bh[D_IN * D_HID];    // bf16(W2L^T) [n][k]
__device__ __align__(16) __nv_bfloat16 g_W1h[D_IN * D_IN];    // w1^T hi [n][k]
__device__ __align__(16) __nv_bfloat16 g_W1l[D_IN * D_IN];    // w1^T lo
__device__ __align__(16) __nv_bfloat16 g_W2h[D_IN * D_IN];    // w2^T hi
__device__ __align__(16) __nv_bfloat16 g_W2l[D_IN * D_IN];    // w2^T lo
__device__ float g_h[(size_t)N_NODES * D_IN];                 // x + aggr
__device__ float g_t[(size_t)N_NODES * D_IN];                 // relu(LN(h@w1+b1))
__device__ int   g_is64;                                      // dtype flag

// ---------------- K-1: detect edge_index dtype ------------------------------
__global__ void detect_idx_kernel(const int* __restrict__ ei32) {
    if (threadIdx.x == 0 && blockIdx.x == 0) {
        int is64 = 1;
        for (int i = 0; i < 64; i++)
            if (ei32[2 * i + 1] != 0) { is64 = 0; break; }
        g_is64 = is64;
    }
}

// ---------------- K0a: fold ew2 @ lew, bf16 hi part -------------------------
__global__ void precompute_kernel(const float* __restrict__ ew2,
                                  const float* __restrict__ lew,
                                  const float* __restrict__ eb2) {
    int idx = blockIdx.x * blockDim.x + threadIdx.x;   // 0..32767
    int k = idx >> 8;      // 0..127 (hid)
    int n = idx & 255;     // 0..255 (out col)
    float s = 0.f;
#pragma unroll 8
    for (int j = 0; j < D_HID; j++)
        s = fmaf(ew2[k * D_HID + j], lew[j * D_IN + n], s);
    g_Bh[n * D_HID + k] = __float2bfloat16(s);
    if (idx < D_IN) {
        float b = 0.f;
        for (int j = 0; j < D_HID; j++)
            b = fmaf(eb2[j], lew[j * D_IN + idx], b);
        g_b2l[idx] = b;
    }
}

// ---------------- K0b: transpose + split node weights -----------------------
__global__ void split_w_kernel(const float* __restrict__ w, int which) {
    __nv_bfloat16* Wh = which ? g_W2h : g_W1h;
    __nv_bfloat16* Wl = which ? g_W2l : g_W1l;
    int idx = blockIdx.x * blockDim.x + threadIdx.x;   // 0..65535
    int k = idx >> 8, n = idx & 255;
    float v = w[k * D_IN + n];
    __nv_bfloat16 hi = __float2bfloat16(v);
    Wh[n * D_IN + k] = hi;
    Wl[n * D_IN + k] = __float2bfloat16(v - __bfloat162float(hi));
}

// ---------------- K1: g_h = x ----------------------------------------------
__global__ void init_h_kernel(const float* __restrict__ x) {
    const size_t total = (size_t)N_NODES * D_IN / 4;
    const float4* xs = (const float4*)x;
    float4* hs = (float4*)g_h;
    for (size_t i = (size_t)blockIdx.x * blockDim.x + threadIdx.x; i < total;
         i += (size_t)gridDim.x * blockDim.x)
        hs[i] = xs[i];
}

// ---------------- K2: edge kernel (64-edge tiles, 2 CTAs/SM) ----------------
// 1-term bf16 (Ah @ Bh^T); B rows PERMUTED so each lane's fragment pair covers
// 4 contiguous global cols -> LDG.128 gather + red.v4 scatter.
// fragment pos j(na,c) holds global col G = 16*(na>>1) + 4*(c>>1) + 2*(na&1) + (c&1)
#define STRIDE_AB 272
#define OFF_BH   0          // 256*272 = 69632
#define OFF_A    69632      // 64*272 = 17408 (single buffer, hi split only)
#define OFF_EW1  87040      // 8192
#define OFF_RAW  95232      // 64*16*4 = 4096
#define OFF_EB1  99328      // 512
#define OFF_B2L  99840      // 1024
#define OFF_LEB  100864     // 1024
#define OFF_POL  101888     // 256
#define OFF_SRC  102144     // 256
#define OFF_DST  102400     // 256
#define EDGE_SMEM 102656
#define EDGE_THREADS 256
#define EDGE_GRID 296       // 2 CTAs per SM

__global__ __launch_bounds__(EDGE_THREADS, 2)
void edge_kernel(const float* __restrict__ x,
                 const void* __restrict__ ei_raw,
                 const float* __restrict__ ea,
                 const float* __restrict__ ew1,
                 const float* __restrict__ eb1,
                 const float* __restrict__ leb) {
    extern __shared__ char smem[];
    const uint32_t smem_u = smem_to_u32(smem);
    float* s_ew1 = (float*)(smem + OFF_EW1);
    float* s_raw = (float*)(smem + OFF_RAW);
    float* s_eb1 = (float*)(smem + OFF_EB1);
    float* s_b2l = (float*)(smem + OFF_B2L);
    float* s_leb = (float*)(smem + OFF_LEB);
    float* s_pol = (float*)(smem + OFF_POL);
    int*   s_src = (int*)(smem + OFF_SRC);
    int*   s_dst = (int*)(smem + OFF_DST);

    const int tid = threadIdx.x;
    const int wid = tid >> 5;              // 0..7
    const int lane = tid & 31;
    const int is64 = g_is64;
    const long long* ei64 = (const long long*)ei_raw;
    const int*       ei32 = (const int*)ei_raw;

    // B staging with N-permutation: global col G -> fragment row position
    for (int w = tid; w < 256 * 64; w += EDGE_THREADS) {
        int G = w >> 6, k2 = w & 63;
        int wnb = G >> 6;            // 64-col block (matches warp wn)
        int gl = G & 63;             // col within block
        int na = 2 * (gl >> 4) + ((gl >> 1) & 1);
        int c  = 2 * ((gl >> 2) & 3) + (gl & 1);
        int n  = wnb * 64 + na * 8 + c;   // fragment row
        *(uint32_t*)(smem + OFF_BH + (uint32_t)n * STRIDE_AB + (uint32_t)k2 * 4u)
            = ((const uint32_t*)g_Bh)[w];
    }
    for (int i = tid; i < D_RAW * D_HID; i += EDGE_THREADS) s_ew1[i] = ew1[i];
    if (tid < D_HID) s_eb1[tid] = eb1[tid];
    if (tid < D_IN) { s_b2l[tid] = g_b2l[tid]; s_leb[tid] = leb[tid]; }
    __syncthreads();

    const int numTiles = N_EDGES / TILE_E;     // 12500
    const int stride = gridDim.x;

    // warp tile for MMA: rows [wm*32,+32), cols [wn*64,+64)
    const int wm = wid & 1;
    const int wn = wid >> 1;                   // 0..3
    const uint32_t a_off = (uint32_t)(wm * 32 + (lane & 15)) * STRIDE_AB +
                           (uint32_t)(lane >> 4) * 16u;
    const uint32_t b4_off = (uint32_t)(wn * 64 + ((lane >> 4) & 1) * 8 +
                                       (lane & 7)) * STRIDE_AB +
                            (uint32_t)((lane >> 3) & 1) * 16u;
    const int q  = lane >> 2;

    for (int t = blockIdx.x; t < numTiles; t += stride) {
        // ---- produce: load 8 edges/warp + stage1 -> A (hi split) ----
        {
            const int e0 = t * TILE_E;
            const int er0 = wid * 8;
            for (int i = lane; i < 8 * 17; i += 32) {
                int le = i / 17, c = i % 17;
                float v = ea[(size_t)(e0 + er0 + le) * 17 + c];
                if (c == 0)
                    s_pol[er0 + le] = fminf(fmaxf(v, 0.f), 1.f) + 0.01f;
                else
                    s_raw[(er0 + le) * D_RAW + (c - 1)] = v;
            }
            if (lane < 8) {
                int sv = is64 ? (int)ei64[e0 + er0 + lane]
                              : ei32[e0 + er0 + lane];
                s_src[er0 + lane] = min(max(sv, 0), N_NODES - 1);
            } else if (lane < 16) {
                int l8 = lane - 8;
                int dv = is64 ? (int)ei64[N_EDGES + e0 + er0 + l8]
                              : ei32[N_EDGES + e0 + er0 + l8];
                s_dst[er0 + l8] = min(max(dv, 0), N_NODES - 1);
            }
            __syncwarp();

            const int c0 = lane * 4;
            float4 a4[8];
            float4 eb4 = *(const float4*)&s_eb1[c0];
#pragma unroll
            for (int e = 0; e < 8; e++) a4[e] = eb4;
#pragma unroll
            for (int kb = 0; kb < 4; kb++) {
                float4 w0 = *(const float4*)&s_ew1[(kb * 4 + 0) * D_HID + c0];
                float4 w1 = *(const float4*)&s_ew1[(kb * 4 + 1) * D_HID + c0];
                float4 w2 = *(const float4*)&s_ew1[(kb * 4 + 2) * D_HID + c0];
                float4 w3 = *(const float4*)&s_ew1[(kb * 4 + 3) * D_HID + c0];
#pragma unroll
                for (int e = 0; e < 8; e++) {
                    float4 r = *(const float4*)&s_raw[(er0 + e) * D_RAW + kb * 4];
                    float4 a = a4[e];
                    a.x = fmaf(r.x, w0.x, a.x); a.y = fmaf(r.x, w0.y, a.y);
                    a.z = fmaf(r.x, w0.z, a.z); a.w = fmaf(r.x, w0.w, a.w);
                    a.x = fmaf(r.y, w1.x, a.x); a.y = fmaf(r.y, w1.y, a.y);
                    a.z = fmaf(r.y, w1.z, a.z); a.w = fmaf(r.y, w1.w, a.w);
                    a.x = fmaf(r.z, w2.x, a.x); a.y = fmaf(r.z, w2.y, a.y);
                    a.z = fmaf(r.z, w2.z, a.z); a.w = fmaf(r.z, w2.w, a.w);
                    a.x = fmaf(r.w, w3.x, a.x); a.y = fmaf(r.w, w3.y, a.y);
                    a.z = fmaf(r.w, w3.z, a.z); a.w = fmaf(r.w, w3.w, a.w);
                    a4[e] = a;
                }
            }
            char* ah = smem + OFF_A + (er0 * STRIDE_AB) + lane * 8;
#pragma unroll
            for (int e = 0; e < 8; e++) {
                float4 a = a4[e];
                __nv_bfloat162 h01, h23;
                h01.x = __float2bfloat16(fmaxf(a.x, 0.f));
                h01.y = __float2bfloat16(fmaxf(a.y, 0.f));
                h23.x = __float2bfloat16(fmaxf(a.z, 0.f));
                h23.y = __float2bfloat16(fmaxf(a.w, 0.f));
                *(uint2*)(ah + e * STRIDE_AB) =
                    make_uint2(*(uint32_t*)&h01, *(uint32_t*)&h23);
            }
        }
        __syncthreads();

        // ---- MMA: D = Ah @ Bh^T ----
        float acc[2][8][4];
#pragma unroll
        for (int ma = 0; ma < 2; ma++)
#pragma unroll
            for (int na = 0; na < 8; na++)
#pragma unroll
                for (int r = 0; r < 4; r++) acc[ma][na][r] = 0.f;

        const uint32_t aBase = smem_u + OFF_A;
#pragma unroll
        for (int ks = 0; ks < 8; ks++) {
            const uint32_t ka = (uint32_t)ks * 32u;
            uint32_t ah0[4], ah1[4];
            ldsm_x4(ah0, aBase + a_off + ka);
            ldsm_x4(ah1, aBase + a_off + 16u * STRIDE_AB + ka);
#pragma unroll
            for (int np = 0; np < 4; np++) {
                uint32_t bq[4];
                ldsm_x4(bq, smem_u + OFF_BH + b4_off +
                            (uint32_t)np * 16u * STRIDE_AB + ka);
                mma_bf16(acc[0][2 * np],     ah0, &bq[0]);
                mma_bf16(acc[1][2 * np],     ah1, &bq[0]);
                mma_bf16(acc[0][2 * np + 1], ah0, &bq[2]);
                mma_bf16(acc[1][2 * np + 1], ah1, &bq[2]);
            }
        }

        // ---- epilogue: 4-wide gather + relu + red.v4 (permuted cols) ----
#pragma unroll
        for (int ma = 0; ma < 2; ma++) {
#pragma unroll
            for (int hl = 0; hl < 2; hl++) {
                const int row = wm * 32 + ma * 16 + q + hl * 8;
                const float s = s_pol[row];
                const float* xr = x + (size_t)s_src[row] * D_IN + wn * 64;
                float* hd = g_h + (size_t)s_dst[row] * D_IN + wn * 64;
#pragma unroll
                for (int p = 0; p < 4; p++) {
                    const int cl = p * 16 + (lane & 3) * 4;
                    const int col = wn * 64 + cl;
                    float4 bb = *(const float4*)&s_b2l[col];
                    float4 ll = *(const float4*)&s_leb[col];
                    float4 xv = *(const float4*)(xr + cl);
                    float m0 = fmaxf(
                        fmaf(s, acc[ma][2 * p][hl * 2 + 0] + bb.x, ll.x) + xv.x,
                        0.f);
                    float m1 = fmaxf(
                        fmaf(s, acc[ma][2 * p][hl * 2 + 1] + bb.y, ll.y) + xv.y,
                        0.f);
                    float m2 = fmaxf(
                        fmaf(s, acc[ma][2 * p + 1][hl * 2 + 0] + bb.z, ll.z) +
                            xv.z, 0.f);
                    float m3 = fmaxf(
                        fmaf(s, acc[ma][2 * p + 1][hl * 2 + 1] + bb.w, ll.w) +
                            xv.w, 0.f);
                    red_v4(hd + cl, m0, m1, m2, m3);
                }
            }
        }
        __syncthreads();
    }
}

// ---------------- node GEMM kernels (HMMA, 3-term bf16 emulation) ----------
#define NOFF_BH   0          // B hi chunk [256n][272B]
#define NOFF_BL   69632
#define NOFF_AH   139264     // A hi chunk [128m][272B]
#define NOFF_AL   174080
#define NOFF_PART 208896     // [128][4][2] f32 partial sums (node1 LN)
#define NOFF_B    212992     // bias 256 f
#define NOFF_LNG  214016
#define NOFF_LNB  215040
#define NODE_SMEM 216064
#define N_TILES_M ((N_NODES + 127) / 128)   // 391

template <bool WITH_LN>
__device__ __forceinline__ void node_gemm_body(
    const float* __restrict__ Asrc, const __nv_bfloat16* __restrict__ Wh,
    const __nv_bfloat16* __restrict__ Wl, const float* __restrict__ bias,
    const float* __restrict__ ln_g, const float* __restrict__ ln_b,
    float* __restrict__ Dst) {
    extern __shared__ char smem[];
    const uint32_t smem_u = smem_to_u32(smem);
    float* s_part = (float*)(smem + NOFF_PART);
    float* s_b    = (float*)(smem + NOFF_B);
    float* s_lng  = (float*)(smem + NOFF_LNG);
    float* s_lnb  = (float*)(smem + NOFF_LNB);

    const int tid = threadIdx.x;
    const int wid = tid >> 5;
    const int lane = tid & 31;
    const int r0 = blockIdx.x * 128;

    if (tid < D_IN) {
        s_b[tid] = bias[tid];
        if (WITH_LN) { s_lng[tid] = ln_g[tid]; s_lnb[tid] = ln_b[tid]; }
    }

    const int wm = wid & 3;
    const int wn = wid >> 2;
    const uint32_t a_off = (uint32_t)(wm * 32 + (lane & 15)) * STRIDE_AB +
                           (uint32_t)(lane >> 4) * 16u;
    const uint32_t b4_off = (uint32_t)(wn * 64 + ((lane >> 4) & 1) * 8 +
                                       (lane & 7)) * STRIDE_AB +
                            (uint32_t)((lane >> 3) & 1) * 16u;
    const int q  = lane >> 2;
    const int cp = (lane & 3) * 2;

    float acc[2][8][4];
#pragma unroll
    for (int ma = 0; ma < 2; ma++)
#pragma unroll
        for (int na = 0; na < 8; na++)
#pragma unroll
            for (int r = 0; r < 4; r++) acc[ma][na][r] = 0.f;

    for (int kc = 0; kc < 2; kc++) {
        for (int i = tid; i < 256 * 16; i += 512) {
            int n = i >> 4, c = i & 15;
            const size_t src = (size_t)n * D_IN + kc * 128 + c * 8;
            *(uint4*)(smem + NOFF_BH + (uint32_t)n * STRIDE_AB + c * 16) =
                *(const uint4*)(Wh + src);
            *(uint4*)(smem + NOFF_BL + (uint32_t)n * STRIDE_AB + c * 16) =
                *(const uint4*)(Wl + src);
        }
        for (int i = tid; i < 128 * 32; i += 512) {
            int r = i >> 5, c4 = i & 31;
            int rr = min(r0 + r, N_NODES - 1);
            float4 v = *(const float4*)&Asrc[(size_t)rr * D_IN + kc * 128 + c4 * 4];
            __nv_bfloat162 h01, h23, l01, l23;
            h01.x = __float2bfloat16(v.x); h01.y = __float2bfloat16(v.y);
            h23.x = __float2bfloat16(v.z); h23.y = __float2bfloat16(v.w);
            l01.x = __float2bfloat16(v.x - __bfloat162float(h01.x));
            l01.y = __float2bfloat16(v.y - __bfloat162float(h01.y));
            l23.x = __float2bfloat16(v.z - __bfloat162float(h23.x));
            l23.y = __float2bfloat16(v.w - __bfloat162float(h23.y));
            uint32_t off = (uint32_t)r * STRIDE_AB + c4 * 8;
            *(uint2*)(smem + NOFF_AH + off) =
                make_uint2(*(uint32_t*)&h01, *(uint32_t*)&h23);
            *(uint2*)(smem + NOFF_AL + off) =
                make_uint2(*(uint32_t*)&l01, *(uint32_t*)&l23);
        }
        __syncthreads();

#pragma unroll
        for (int ks = 0; ks < 8; ks++) {
            const uint32_t ka = (uint32_t)ks * 32u;
            uint32_t ah0[4], ah1[4], al0[4], al1[4];
            ldsm_x4(ah0, smem_u + NOFF_AH + a_off + ka);
            ldsm_x4(ah1, smem_u + NOFF_AH + a_off + 16u * STRIDE_AB + ka);
            ldsm_x4(al0, smem_u + NOFF_AL + a_off + ka);
            ldsm_x4(al1, smem_u + NOFF_AL + a_off + 16u * STRIDE_AB + ka);
#pragma unroll
            for (int np = 0; np < 4; np++) {
                uint32_t bh[4], bl[4];
                const uint32_t bo = b4_off + (uint32_t)np * 16u * STRIDE_AB + ka;
                ldsm_x4(bh, smem_u + NOFF_BH + bo);
                ldsm_x4(bl, smem_u + NOFF_BL + bo);
                mma_bf16(acc[0][2 * np],     ah0, &bh[0]);
                mma_bf16(acc[1][2 * np],     ah1, &bh[0]);
                mma_bf16(acc[0][2 * np],     al0, &bh[0]);
                mma_bf16(acc[1][2 * np],     al1, &bh[0]);
                mma_bf16(acc[0][2 * np],     ah0, &bl[0]);
                mma_bf16(acc[1][2 * np],     ah1, &bl[0]);
                mma_bf16(acc[0][2 * np + 1], ah0, &bh[2]);
                mma_bf16(acc[1][2 * np + 1], ah1, &bh[2]);
                mma_bf16(acc[0][2 * np + 1], al0, &bh[2]);
                mma_bf16(acc[1][2 * np + 1], al1, &bh[2]);
                mma_bf16(acc[0][2 * np + 1], ah0, &bl[2]);
                mma_bf16(acc[1][2 * np + 1], ah1, &bl[2]);
            }
        }
        __syncthreads();
    }

    float bcol[8][2];
#pragma unroll
    for (int na = 0; na < 8; na++) {
        bcol[na][0] = s_b[wn * 64 + na * 8 + cp];
        bcol[na][1] = s_b[wn * 64 + na * 8 + cp + 1];
    }
#pragma unroll
    for (int ma = 0; ma < 2; ma++)
#pragma unroll
        for (int na = 0; na < 8; na++)
#pragma unroll
            for (int hl = 0; hl < 2; hl++) {
                acc[ma][na][hl * 2 + 0] += bcol[na][0];
                acc[ma][na][hl * 2 + 1] += bcol[na][1];
            }

    if (WITH_LN) {
#pragma unroll
        for (int ma = 0; ma < 2; ma++)
#pragma unroll
            for (int hl = 0; hl < 2; hl++) {
                float s = 0.f, ss = 0.f;
#pragma unroll
                for (int na = 0; na < 8; na++) {
                    float v0 = acc[ma][na][hl * 2 + 0];
                    float v1 = acc[ma][na][hl * 2 + 1];
                    s += v0 + v1;
                    ss = fmaf(v0, v0, ss); ss = fmaf(v1, v1, ss);
                }
                s  += __shfl_xor_sync(0xffffffffu, s, 1);
                s  += __shfl_xor_sync(0xffffffffu, s, 2);
                ss += __shfl_xor_sync(0xffffffffu, ss, 1);
                ss += __shfl_xor_sync(0xffffffffu, ss, 2);
                if ((lane & 3) == 0) {
                    const int row = wm * 32 + ma * 16 + hl * 8 + q;
                    *(float2*)&s_part[row * 8 + wn * 2] = make_float2(s, ss);
                }
            }
        __syncthreads();

#pragma unroll
        for (int ma = 0; ma < 2; ma++)
#pragma unroll
            for (int hl = 0; hl < 2; hl++) {
                const int row = wm * 32 + ma * 16 + hl * 8 + q;
                float sum = 0.f, ssum = 0.f;
#pragma unroll
                for (int w = 0; w < 4; w++) {
                    float2 p = *(const float2*)&s_part[row * 8 + w * 2];
                    sum += p.x; ssum += p.y;
                }
                const float mu = sum * (1.f / D_IN);
                const float var =
                    fmaxf(ssum * (1.f / D_IN) - mu * mu, 0.f);
                const float rstd = rsqrtf(var + LN_EPS);
                const int grow = r0 + row;
                if (grow < N_NODES) {
#pragma unroll
                    for (int na = 0; na < 8; na++) {
                        const int col = wn * 64 + na * 8 + cp;
                        float g0 = s_lng[col], g1 = s_lng[col + 1];
                        float l0 = s_lnb[col], l1 = s_lnb[col + 1];
                        float o0 = fmaxf(
                            fmaf((acc[ma][na][hl * 2] - mu) * rstd, g0, l0), 0.f);
                        float o1 = fmaxf(
                            fmaf((acc[ma][na][hl * 2 + 1] - mu) * rstd, g1, l1),
                            0.f);
                        *(float2*)&Dst[(size_t)grow * D_IN + col] =
                            make_float2(o0, o1);
                    }
                }
            }
    } else {
#pragma unroll
        for (int ma = 0; ma < 2; ma++)
#pragma unroll
            for (int hl = 0; hl < 2; hl++) {
                const int row = wm * 32 + ma * 16 + hl * 8 + q;
                const int grow = r0 + row;
                if (grow < N_NODES) {
#pragma unroll
                    for (int na = 0; na < 8; na++) {
                        const int col = wn * 64 + na * 8 + cp;
                        *(float2*)&Dst[(size_t)grow * D_IN + col] =
                            make_float2(acc[ma][na][hl * 2],
                                        acc[ma][na][hl * 2 + 1]);
                    }
                }
            }
    }
}

__global__ __launch_bounds__(512, 1)
void node1_kernel(const float* __restrict__ b1, const float* __restrict__ ln_g,
                  const float* __restrict__ ln_b) {
    node_gemm_body<true>(g_h, g_W1h, g_W1l, b1, ln_g, ln_b, g_t);
}

__global__ __launch_bounds__(512, 1)
void node2_kernel(const float* __restrict__ b2, float* __restrict__ out) {
    node_gemm_body<false>(g_t, g_W2h, g_W2l, b2, nullptr, nullptr, out);
}

// ---------------- launcher --------------------------------------------------
extern "C" void kernel_launch(void* const* d_in, const int* in_sizes, int n_in,
                              void* d_out, int out_size) {
    const float* x    = (const float*)d_in[0];
    const void*  ei   = d_in[1];
    const float* ea   = (const float*)d_in[2];
    const float* ew1  = (const float*)d_in[3];
    const float* eb1  = (const float*)d_in[4];
    const float* ew2  = (const float*)d_in[5];
    const float* eb2  = (const float*)d_in[6];
    const float* lew  = (const float*)d_in[7];
    const float* leb  = (const float*)d_in[8];
    const float* w1   = (const float*)d_in[9];
    const float* b1   = (const float*)d_in[10];
    const float* ln_g = (const float*)d_in[11];
    const float* ln_b = (const float*)d_in[12];
    const float* w2   = (const float*)d_in[13];
    const float* b2   = (const float*)d_in[14];
    float* out = (float*)d_out;

    cudaFuncSetAttribute(edge_kernel, cudaFuncAttributeMaxDynamicSharedMemorySize,
                         EDGE_SMEM);
    cudaFuncSetAttribute(node1_kernel, cudaFuncAttributeMaxDynamicSharedMemorySize,
                         NODE_SMEM);
    cudaFuncSetAttribute(node2_kernel, cudaFuncAttributeMaxDynamicSharedMemorySize,
                         NODE_SMEM);

    detect_idx_kernel<<<1, 32>>>((const int*)ei);
    precompute_kernel<<<128, 256>>>(ew2, lew, eb2);
    split_w_kernel<<<256, 256>>>(w1, 0);
    split_w_kernel<<<256, 256>>>(w2, 1);
    init_h_kernel<<<1184, 256>>>(x);
    edge_kernel<<<EDGE_GRID, EDGE_THREADS, EDGE_SMEM>>>(x, ei, ea, ew1, eb1, leb);
    node1_kernel<<<N_TILES_M, 512, NODE_SMEM>>>(b1, ln_g, ln_b);
    node2_kernel<<<N_TILES_M, 512, NODE_SMEM>>>(b2, out);
}